// round 1
// baseline (speedup 1.0000x reference)
#include <cuda_runtime.h>
#include <math.h>

// Problem constants
#define BB 4
#define SS 2048
#define DD 512
#define HH 512
#define EE 8
#define TT 8192          // tokens
#define KSEL 2
#define NPAIR (TT*KSEL)  // 16384

// GEMM tiling
#define TM 128
#define TN 128
#define TKK 16
#define NKT (512/TKK)

// ---------------- scratch (global device memory; no allocs) ----------------
__device__ int   g_count[EE];
__device__ int   g_offset[EE+1];
__device__ int   g_cursor[EE];
__device__ int   g_rowtok[NPAIR];     // slot -> token id
__device__ int   g_pos[NPAIR];        // pair (t*2+k) -> slot
__device__ int   g_topi[NPAIR];       // pair -> expert id
__device__ float g_gatew[NPAIR];      // pair -> gate weight
__device__ __align__(16) float g_hbuf[(size_t)NPAIR*HH]; // 33.5 MB
__device__ __align__(16) float g_ybuf[(size_t)NPAIR*DD]; // 33.5 MB

// ---------------- kernel 0: zero counters ----------------
__global__ void k_zero() {
    int i = threadIdx.x;
    if (i < EE) { g_count[i] = 0; g_cursor[i] = 0; }
}

// ---------------- kernel 1: gating ----------------
// 1 warp per token; 4 tokens per 128-thread block.
__global__ void k_gating(const float* __restrict__ x, const float* __restrict__ Wg) {
    int warp = threadIdx.x >> 5, lane = threadIdx.x & 31;
    int t = blockIdx.x * 4 + warp;
    if (t >= TT) return;

    float acc[EE];
#pragma unroll
    for (int e = 0; e < EE; e++) acc[e] = 0.f;

    const float* xr = x + (size_t)t * DD;
    for (int d = lane; d < DD; d += 32) {
        float xv = xr[d];
        float4 w0 = *(const float4*)(Wg + (size_t)d * EE);
        float4 w1 = *(const float4*)(Wg + (size_t)d * EE + 4);
        acc[0] += xv * w0.x; acc[1] += xv * w0.y;
        acc[2] += xv * w0.z; acc[3] += xv * w0.w;
        acc[4] += xv * w1.x; acc[5] += xv * w1.y;
        acc[6] += xv * w1.z; acc[7] += xv * w1.w;
    }
#pragma unroll
    for (int off = 16; off; off >>= 1)
#pragma unroll
        for (int e = 0; e < EE; e++)
            acc[e] += __shfl_down_sync(0xffffffffu, acc[e], off);

    if (lane == 0) {
        int i0 = 0; float v0 = acc[0];
#pragma unroll
        for (int e = 1; e < EE; e++) if (acc[e] > v0) { v0 = acc[e]; i0 = e; }
        int i1 = -1; float v1 = -INFINITY;
#pragma unroll
        for (int e = 0; e < EE; e++) if (e != i0 && acc[e] > v1) { v1 = acc[e]; i1 = e; }
        float e1 = expf(v1 - v0);
        float w0w = 1.f / (1.f + e1);
        float w1w = e1 * w0w;
        g_topi[2*t]   = i0; g_topi[2*t+1] = i1;
        g_gatew[2*t]  = w0w; g_gatew[2*t+1] = w1w;
        atomicAdd(&g_count[i0], 1);
        atomicAdd(&g_count[i1], 1);
    }
}

// ---------------- kernel 2: prefix sum over 8 experts ----------------
__global__ void k_offsets() {
    if (threadIdx.x == 0) {
        int s = 0;
        for (int e = 0; e < EE; e++) { g_offset[e] = s; g_cursor[e] = s; s += g_count[e]; }
        g_offset[EE] = s;
    }
}

// ---------------- kernel 3: scatter pairs into compact buckets ----------------
__global__ void k_scatter() {
    int p = blockIdx.x * blockDim.x + threadIdx.x;
    if (p >= NPAIR) return;
    int e = g_topi[p];
    int slot = atomicAdd(&g_cursor[e], 1);
    g_rowtok[slot] = p >> 1;
    g_pos[p] = slot;
}

// ---------------- kernel 4: grouped GEMM ----------------
// MODE 0: hbuf[base+m] = relu(x[rowtok] @ W1[e] + b1[e])
// MODE 1: ybuf[base+m] = hbuf[base+m] @ W2[e] + b2[e]
template <int MODE>
__global__ void __launch_bounds__(256, 2)
k_gemm(const float* __restrict__ Xg, const float* __restrict__ Wbase,
       const float* __restrict__ Bias) {
    const int e = blockIdx.z;
    const int count = g_count[e];
    const int m0 = blockIdx.y * TM;
    if (m0 >= count) return;
    const int base = g_offset[e];
    const int n0 = blockIdx.x * TN;
    const float* Wp = Wbase + (size_t)e * 512 * 512;
    const float* bp = Bias + (size_t)e * 512;

    __shared__ float As[TKK][TM];
    __shared__ float Bs[TKK][TN];

    const int tid = threadIdx.x;
    const int tx = tid & 15, ty = tid >> 4;

    float4 aReg[2], bReg[2];

    auto loadA = [&](int kt) {
#pragma unroll
        for (int p = 0; p < 2; p++) {
            int idx = tid + p * 256;
            int row = idx >> 2, kk = (idx & 3) * 4;
            int m = m0 + row;
            if (m < count) {
                const float* src;
                if (MODE == 0) src = Xg + (size_t)g_rowtok[base + m] * DD;
                else           src = g_hbuf + (size_t)(base + m) * HH;
                aReg[p] = *(const float4*)(src + kt * TKK + kk);
            } else {
                aReg[p] = make_float4(0.f, 0.f, 0.f, 0.f);
            }
        }
    };
    auto loadB = [&](int kt) {
#pragma unroll
        for (int p = 0; p < 2; p++) {
            int idx = tid + p * 256;
            int bk = idx >> 5, bn = (idx & 31) * 4;
            bReg[p] = *(const float4*)(Wp + (size_t)(kt * TKK + bk) * 512 + n0 + bn);
        }
    };
    auto storeAB = [&]() {
#pragma unroll
        for (int p = 0; p < 2; p++) {
            int idx = tid + p * 256;
            int row = idx >> 2, kk = (idx & 3) * 4;
            As[kk + 0][row] = aReg[p].x;
            As[kk + 1][row] = aReg[p].y;
            As[kk + 2][row] = aReg[p].z;
            As[kk + 3][row] = aReg[p].w;
        }
#pragma unroll
        for (int p = 0; p < 2; p++) {
            int idx = tid + p * 256;
            int bk = idx >> 5, bn = (idx & 31) * 4;
            *(float4*)&Bs[bk][bn] = bReg[p];
        }
    };

    float acc[8][8];
#pragma unroll
    for (int i = 0; i < 8; i++)
#pragma unroll
        for (int j = 0; j < 8; j++) acc[i][j] = 0.f;

    loadA(0); loadB(0);
    for (int kt = 0; kt < NKT; kt++) {
        __syncthreads();
        storeAB();
        __syncthreads();
        if (kt + 1 < NKT) { loadA(kt + 1); loadB(kt + 1); }
#pragma unroll
        for (int k = 0; k < TKK; k++) {
            float a[8], b[8];
            *(float4*)(a)     = *(const float4*)&As[k][ty * 8];
            *(float4*)(a + 4) = *(const float4*)&As[k][ty * 8 + 4];
            *(float4*)(b)     = *(const float4*)&Bs[k][tx * 8];
            *(float4*)(b + 4) = *(const float4*)&Bs[k][tx * 8 + 4];
#pragma unroll
            for (int i = 0; i < 8; i++)
#pragma unroll
                for (int j = 0; j < 8; j++) acc[i][j] += a[i] * b[j];
        }
    }

    // epilogue
    float bias[8];
#pragma unroll
    for (int j = 0; j < 8; j++) bias[j] = bp[n0 + tx * 8 + j];
#pragma unroll
    for (int i = 0; i < 8; i++) {
        int m = m0 + ty * 8 + i;
        if (m >= count) continue;
        float v[8];
#pragma unroll
        for (int j = 0; j < 8; j++) {
            float z = acc[i][j] + bias[j];
            v[j] = (MODE == 0) ? fmaxf(z, 0.f) : z;
        }
        float* dst = (MODE == 0 ? g_hbuf : g_ybuf) + (size_t)(base + m) * 512 + n0 + tx * 8;
        *(float4*)(dst)     = *(float4*)(v);
        *(float4*)(dst + 4) = *(float4*)(v + 4);
    }
}

// ---------------- kernel 5: LayerNorm + weighted combine ----------------
// one block (256 threads) per token; each thread owns d = tid and tid+256
__global__ void k_combine(const float* __restrict__ gamma,
                          const float* __restrict__ beta,
                          float* __restrict__ out) {
    int t = blockIdx.x;
    int tid = threadIdx.x;
    int lane = tid & 31, wid = tid >> 5;
    __shared__ float wred[8][2];
    __shared__ float red[2];

    float o0 = 0.f, o1 = 0.f;
#pragma unroll
    for (int k = 0; k < KSEL; k++) {
        int slot = g_pos[2 * t + k];
        int e = g_topi[2 * t + k];
        float w = g_gatew[2 * t + k];
        const float* yr = g_ybuf + (size_t)slot * 512;
        float y0 = yr[tid], y1 = yr[tid + 256];
        float s = y0 + y1, ss = y0 * y0 + y1 * y1;
#pragma unroll
        for (int off = 16; off; off >>= 1) {
            s  += __shfl_down_sync(0xffffffffu, s, off);
            ss += __shfl_down_sync(0xffffffffu, ss, off);
        }
        if (lane == 0) { wred[wid][0] = s; wred[wid][1] = ss; }
        __syncthreads();
        if (tid == 0) {
            float ts = 0.f, tss = 0.f;
#pragma unroll
            for (int i = 0; i < 8; i++) { ts += wred[i][0]; tss += wred[i][1]; }
            red[0] = ts; red[1] = tss;
        }
        __syncthreads();
        float mu = red[0] * (1.f / 512.f);
        float var = red[1] * (1.f / 512.f) - mu * mu;
        float rstd = rsqrtf(var + 1e-5f);
        const float* gp = gamma + (size_t)e * 512;
        const float* bp = beta + (size_t)e * 512;
        o0 += w * ((y0 - mu) * rstd * gp[tid] + bp[tid]);
        o1 += w * ((y1 - mu) * rstd * gp[tid + 256] + bp[tid + 256]);
        __syncthreads();
    }
    out[(size_t)t * 512 + tid] = o0;
    out[(size_t)t * 512 + tid + 256] = o1;
}

// ---------------- launch ----------------
extern "C" void kernel_launch(void* const* d_in, const int* in_sizes, int n_in,
                              void* d_out, int out_size) {
    const float* x     = (const float*)d_in[0];
    const float* Wg    = (const float*)d_in[1];
    const float* W1    = (const float*)d_in[2];
    const float* b1    = (const float*)d_in[3];
    const float* W2    = (const float*)d_in[4];
    const float* b2    = (const float*)d_in[5];
    const float* gamma = (const float*)d_in[6];
    const float* beta  = (const float*)d_in[7];
    float* out = (float*)d_out;

    k_zero<<<1, 32>>>();
    k_gating<<<TT / 4, 128>>>(x, Wg);
    k_offsets<<<1, 1>>>();
    k_scatter<<<NPAIR / 256, 256>>>();
    dim3 gg(512 / TN, TT / TM, EE);   // 4 x 64 x 8 tiles (early-exit beyond count)
    k_gemm<0><<<gg, 256>>>(x, W1, b1);
    k_gemm<1><<<gg, 256>>>(nullptr, W2, b2);
    k_combine<<<TT, 256>>>(gamma, beta, out);
}

// round 2
// speedup vs baseline: 2.6879x; 2.6879x over previous
#include <cuda_runtime.h>
#include <math.h>
#include <stdint.h>

// Problem constants
#define BB 4
#define SS 2048
#define DD 512
#define HH 512
#define EE 8
#define TT 8192          // tokens
#define KSEL 2
#define NPAIR (TT*KSEL)  // 16384

// GEMM tiling
#define BM 128
#define BN 128
#define BK 32
#define NKT (512/BK)     // 16 k-tiles
#define APAD 4
#define BPAD 8
#define ALD (BK+APAD)    // 36 floats per A row
#define BLD (BN+BPAD)    // 136 floats per B row
#define ASZ (BM*ALD)     // floats per A buffer
#define BSZ (BK*BLD)     // floats per B buffer
#define SMEM_BYTES ((2*ASZ + 2*BSZ)*4)

// ---------------- scratch ----------------
__device__ int   g_count[EE];
__device__ int   g_offset[EE+1];
__device__ int   g_cursor[EE];
__device__ int   g_rowtok[NPAIR];
__device__ int   g_pos[NPAIR];
__device__ int   g_topi[NPAIR];
__device__ float g_gatew[NPAIR];
__device__ __align__(16) float g_hbuf[(size_t)NPAIR*HH];
__device__ __align__(16) float g_ybuf[(size_t)NPAIR*DD];
__device__ __align__(16) float g_xr[(size_t)TT*DD];        // tf32-rounded x
__device__ __align__(16) float g_w1r[(size_t)EE*DD*HH];    // tf32-rounded W1
__device__ __align__(16) float g_w2r[(size_t)EE*HH*DD];    // tf32-rounded W2

__device__ __forceinline__ float rna_tf32(float f) {
    uint32_t r;
    asm("cvt.rna.tf32.f32 %0, %1;" : "=r"(r) : "f"(f));
    return __uint_as_float(r);
}

// ---------------- kernel: tf32 rounding copy ----------------
__global__ void k_round(const float* __restrict__ src, float* __restrict__ dst, int n4) {
    int i = blockIdx.x * blockDim.x + threadIdx.x;
    if (i >= n4) return;
    float4 v = ((const float4*)src)[i];
    v.x = rna_tf32(v.x); v.y = rna_tf32(v.y);
    v.z = rna_tf32(v.z); v.w = rna_tf32(v.w);
    ((float4*)dst)[i] = v;
}

// ---------------- kernel 0: zero counters ----------------
__global__ void k_zero() {
    int i = threadIdx.x;
    if (i < EE) { g_count[i] = 0; g_cursor[i] = 0; }
}

// ---------------- kernel 1: gating ----------------
__global__ void k_gating(const float* __restrict__ x, const float* __restrict__ Wg) {
    int warp = threadIdx.x >> 5, lane = threadIdx.x & 31;
    int t = blockIdx.x * 4 + warp;
    if (t >= TT) return;

    float acc[EE];
#pragma unroll
    for (int e = 0; e < EE; e++) acc[e] = 0.f;

    const float* xr = x + (size_t)t * DD;
    for (int d = lane; d < DD; d += 32) {
        float xv = xr[d];
        float4 w0 = *(const float4*)(Wg + (size_t)d * EE);
        float4 w1 = *(const float4*)(Wg + (size_t)d * EE + 4);
        acc[0] += xv * w0.x; acc[1] += xv * w0.y;
        acc[2] += xv * w0.z; acc[3] += xv * w0.w;
        acc[4] += xv * w1.x; acc[5] += xv * w1.y;
        acc[6] += xv * w1.z; acc[7] += xv * w1.w;
    }
#pragma unroll
    for (int off = 16; off; off >>= 1)
#pragma unroll
        for (int e = 0; e < EE; e++)
            acc[e] += __shfl_down_sync(0xffffffffu, acc[e], off);

    if (lane == 0) {
        int i0 = 0; float v0 = acc[0];
#pragma unroll
        for (int e = 1; e < EE; e++) if (acc[e] > v0) { v0 = acc[e]; i0 = e; }
        int i1 = -1; float v1 = -INFINITY;
#pragma unroll
        for (int e = 0; e < EE; e++) if (e != i0 && acc[e] > v1) { v1 = acc[e]; i1 = e; }
        float e1 = expf(v1 - v0);
        float w0w = 1.f / (1.f + e1);
        float w1w = e1 * w0w;
        g_topi[2*t]   = i0; g_topi[2*t+1] = i1;
        g_gatew[2*t]  = w0w; g_gatew[2*t+1] = w1w;
        atomicAdd(&g_count[i0], 1);
        atomicAdd(&g_count[i1], 1);
    }
}

// ---------------- kernel 2: prefix sum ----------------
__global__ void k_offsets() {
    if (threadIdx.x == 0) {
        int s = 0;
        for (int e = 0; e < EE; e++) { g_offset[e] = s; g_cursor[e] = s; s += g_count[e]; }
        g_offset[EE] = s;
    }
}

// ---------------- kernel 3: scatter ----------------
__global__ void k_scatter() {
    int p = blockIdx.x * blockDim.x + threadIdx.x;
    if (p >= NPAIR) return;
    int e = g_topi[p];
    int slot = atomicAdd(&g_cursor[e], 1);
    g_rowtok[slot] = p >> 1;
    g_pos[p] = slot;
}

// ---------------- cp.async helpers ----------------
__device__ __forceinline__ void cp_async16(uint32_t smem_addr, const void* gptr, int src_bytes) {
    asm volatile("cp.async.cg.shared.global [%0], [%1], 16, %2;"
                 :: "r"(smem_addr), "l"(gptr), "r"(src_bytes));
}
__device__ __forceinline__ void cp_commit() {
    asm volatile("cp.async.commit_group;");
}

// ---------------- kernel 4: TF32 tensor-core grouped GEMM ----------------
// MODE 0: hbuf = rna(relu(xr[rowtok] @ W1r[e] + b1[e]))
// MODE 1: ybuf = hbuf @ W2r[e] + b2[e]
template <int MODE>
__global__ void __launch_bounds__(256, 2)
k_gemm(const float* __restrict__ Wbase, const float* __restrict__ Bias) {
    const int e = blockIdx.z;
    const int count = g_count[e];
    const int m0 = blockIdx.y * BM;
    if (m0 >= count) return;
    const int base = g_offset[e];
    const int n0 = blockIdx.x * BN;
    const float* Wp = Wbase + (size_t)e * 512 * 512;
    const float* bp = Bias + (size_t)e * 512;

    extern __shared__ float smem[];
    float* As = smem;             // 2 buffers of ASZ
    float* Bs = smem + 2 * ASZ;   // 2 buffers of BSZ
    uint32_t suA = (uint32_t)__cvta_generic_to_shared(As);
    uint32_t suB = (uint32_t)__cvta_generic_to_shared(Bs);

    const int tid = threadIdx.x;
    const int lane = tid & 31, wid = tid >> 5;
    const int warp_m = wid & 3, warp_n = wid >> 2;
    const int gid = lane >> 2, tk = lane & 3;

    // precompute per-thread gmem row pointers (k-tile independent rows)
    const float* aptr[4]; int apred[4];
    uint32_t adst[4];
#pragma unroll
    for (int p = 0; p < 4; p++) {
        int idx = tid + p * 256;
        int row = idx >> 3;           // 0..127
        int col = (idx & 7) * 4;      // 0,4,..,28
        int m = m0 + row;
        if (m < count) {
            if (MODE == 0) aptr[p] = g_xr + (size_t)g_rowtok[base + m] * DD + col;
            else           aptr[p] = g_hbuf + (size_t)(base + m) * HH + col;
            apred[p] = 16;
        } else {
            aptr[p] = g_xr;   // valid dummy, zero-fill
            apred[p] = 0;
        }
        adst[p] = suA + (uint32_t)((row * ALD + col) * 4);
    }
    const float* bptr[4];
    uint32_t bdst[4];
#pragma unroll
    for (int p = 0; p < 4; p++) {
        int idx = tid + p * 256;
        int row = idx >> 5;           // 0..31 (k within tile)
        int col = (idx & 31) * 4;     // 0..124
        bptr[p] = Wp + (size_t)row * 512 + n0 + col;
        bdst[p] = suB + (uint32_t)((row * BLD + col) * 4);
    }

    auto issue = [&](int kt, int buf) {
        uint32_t aoff = (uint32_t)(buf * ASZ * 4);
        uint32_t boff = (uint32_t)(buf * BSZ * 4);
        int kshift = kt * BK;
#pragma unroll
        for (int p = 0; p < 4; p++)
            cp_async16(adst[p] + aoff, aptr[p] + kshift, apred[p]);
#pragma unroll
        for (int p = 0; p < 4; p++)
            cp_async16(bdst[p] + boff, bptr[p] + (size_t)kshift * 512, 16);
        cp_commit();
    };

    float acc[2][8][4];
#pragma unroll
    for (int mf = 0; mf < 2; mf++)
#pragma unroll
        for (int nf = 0; nf < 8; nf++)
#pragma unroll
            for (int q = 0; q < 4; q++) acc[mf][nf][q] = 0.f;

    issue(0, 0);

    for (int kt = 0; kt < NKT; kt++) {
        if (kt + 1 < NKT) {
            issue(kt + 1, (kt + 1) & 1);
            asm volatile("cp.async.wait_group 1;");
        } else {
            asm volatile("cp.async.wait_group 0;");
        }
        __syncthreads();

        const float* Ab = As + (kt & 1) * ASZ;
        const float* Bb = Bs + (kt & 1) * BSZ;

#pragma unroll
        for (int ks = 0; ks < 4; ks++) {
            uint32_t a[2][4];
#pragma unroll
            for (int mf = 0; mf < 2; mf++) {
                int r = warp_m * 32 + mf * 16 + gid;
                int kc = ks * 8 + tk;
                a[mf][0] = __float_as_uint(Ab[r * ALD + kc]);
                a[mf][1] = __float_as_uint(Ab[(r + 8) * ALD + kc]);
                a[mf][2] = __float_as_uint(Ab[r * ALD + kc + 4]);
                a[mf][3] = __float_as_uint(Ab[(r + 8) * ALD + kc + 4]);
            }
            uint32_t b[8][2];
#pragma unroll
            for (int nf = 0; nf < 8; nf++) {
                int c = warp_n * 64 + nf * 8 + gid;
                int kr = ks * 8 + tk;
                b[nf][0] = __float_as_uint(Bb[kr * BLD + c]);
                b[nf][1] = __float_as_uint(Bb[(kr + 4) * BLD + c]);
            }
#pragma unroll
            for (int mf = 0; mf < 2; mf++)
#pragma unroll
                for (int nf = 0; nf < 8; nf++) {
                    asm volatile(
                        "mma.sync.aligned.m16n8k8.row.col.f32.tf32.tf32.f32 "
                        "{%0,%1,%2,%3}, {%4,%5,%6,%7}, {%8,%9}, {%0,%1,%2,%3};"
                        : "+f"(acc[mf][nf][0]), "+f"(acc[mf][nf][1]),
                          "+f"(acc[mf][nf][2]), "+f"(acc[mf][nf][3])
                        : "r"(a[mf][0]), "r"(a[mf][1]), "r"(a[mf][2]), "r"(a[mf][3]),
                          "r"(b[nf][0]), "r"(b[nf][1]));
                }
        }
        __syncthreads();
    }

    // epilogue
    float* outbuf = (MODE == 0) ? g_hbuf : g_ybuf;
#pragma unroll
    for (int nf = 0; nf < 8; nf++) {
        int c = n0 + warp_n * 64 + nf * 8 + tk * 2;
        float2 bv = *(const float2*)(bp + c);
#pragma unroll
        for (int mf = 0; mf < 2; mf++) {
            int r0 = m0 + warp_m * 32 + mf * 16 + gid;
            if (r0 < count) {
                float2 v;
                v.x = acc[mf][nf][0] + bv.x;
                v.y = acc[mf][nf][1] + bv.y;
                if (MODE == 0) {
                    v.x = rna_tf32(fmaxf(v.x, 0.f));
                    v.y = rna_tf32(fmaxf(v.y, 0.f));
                }
                *(float2*)(outbuf + (size_t)(base + r0) * 512 + c) = v;
            }
            int r1 = r0 + 8;
            if (r1 < count) {
                float2 v;
                v.x = acc[mf][nf][2] + bv.x;
                v.y = acc[mf][nf][3] + bv.y;
                if (MODE == 0) {
                    v.x = rna_tf32(fmaxf(v.x, 0.f));
                    v.y = rna_tf32(fmaxf(v.y, 0.f));
                }
                *(float2*)(outbuf + (size_t)(base + r1) * 512 + c) = v;
            }
        }
    }
}

// ---------------- kernel 5: LayerNorm + combine ----------------
__global__ void k_combine(const float* __restrict__ gamma,
                          const float* __restrict__ beta,
                          float* __restrict__ out) {
    int t = blockIdx.x;
    int tid = threadIdx.x;
    int lane = tid & 31, wid = tid >> 5;
    __shared__ float wred[8][2];
    __shared__ float red[2];

    float o0 = 0.f, o1 = 0.f;
#pragma unroll
    for (int k = 0; k < KSEL; k++) {
        int slot = g_pos[2 * t + k];
        int e = g_topi[2 * t + k];
        float w = g_gatew[2 * t + k];
        const float* yr = g_ybuf + (size_t)slot * 512;
        float y0 = yr[tid], y1 = yr[tid + 256];
        float s = y0 + y1, ss = y0 * y0 + y1 * y1;
#pragma unroll
        for (int off = 16; off; off >>= 1) {
            s  += __shfl_down_sync(0xffffffffu, s, off);
            ss += __shfl_down_sync(0xffffffffu, ss, off);
        }
        if (lane == 0) { wred[wid][0] = s; wred[wid][1] = ss; }
        __syncthreads();
        if (tid == 0) {
            float ts = 0.f, tss = 0.f;
#pragma unroll
            for (int i = 0; i < 8; i++) { ts += wred[i][0]; tss += wred[i][1]; }
            red[0] = ts; red[1] = tss;
        }
        __syncthreads();
        float mu = red[0] * (1.f / 512.f);
        float var = red[1] * (1.f / 512.f) - mu * mu;
        float rstd = rsqrtf(var + 1e-5f);
        const float* gp = gamma + (size_t)e * 512;
        const float* bpp = beta + (size_t)e * 512;
        o0 += w * ((y0 - mu) * rstd * gp[tid] + bpp[tid]);
        o1 += w * ((y1 - mu) * rstd * gp[tid + 256] + bpp[tid + 256]);
        __syncthreads();
    }
    out[(size_t)t * 512 + tid] = o0;
    out[(size_t)t * 512 + tid + 256] = o1;
}

// ---------------- launch ----------------
extern "C" void kernel_launch(void* const* d_in, const int* in_sizes, int n_in,
                              void* d_out, int out_size) {
    const float* x     = (const float*)d_in[0];
    const float* Wg    = (const float*)d_in[1];
    const float* W1    = (const float*)d_in[2];
    const float* b1    = (const float*)d_in[3];
    const float* W2    = (const float*)d_in[4];
    const float* b2    = (const float*)d_in[5];
    const float* gamma = (const float*)d_in[6];
    const float* beta  = (const float*)d_in[7];
    float* out = (float*)d_out;

    static int configured = 0;
    if (!configured) {
        cudaFuncSetAttribute(k_gemm<0>, cudaFuncAttributeMaxDynamicSharedMemorySize, SMEM_BYTES);
        cudaFuncSetAttribute(k_gemm<1>, cudaFuncAttributeMaxDynamicSharedMemorySize, SMEM_BYTES);
        configured = 1;
    }

    float* xr;  cudaGetSymbolAddress((void**)&xr,  g_xr);
    float* w1r; cudaGetSymbolAddress((void**)&w1r, g_w1r);
    float* w2r; cudaGetSymbolAddress((void**)&w2r, g_w2r);

    // tf32-round x, W1, W2
    k_round<<<(TT*DD/4 + 255)/256, 256>>>(x,  xr,  TT*DD/4);
    k_round<<<(EE*DD*HH/4 + 255)/256, 256>>>(W1, w1r, EE*DD*HH/4);
    k_round<<<(EE*HH*DD/4 + 255)/256, 256>>>(W2, w2r, EE*HH*DD/4);

    k_zero<<<1, 32>>>();
    k_gating<<<TT / 4, 128>>>(x, Wg);
    k_offsets<<<1, 1>>>();
    k_scatter<<<NPAIR / 256, 256>>>();

    dim3 gg(BN == 128 ? 4 : 512 / BN, NPAIR / BM, EE);  // 4 x 128 x 8, early-exit on count
    k_gemm<0><<<gg, 256, SMEM_BYTES>>>(w1r, b1);
    k_gemm<1><<<gg, 256, SMEM_BYTES>>>(w2r, b2);
    k_combine<<<TT, 256>>>(gamma, beta, out);
}

// round 4
// speedup vs baseline: 4.1064x; 1.5277x over previous
#include <cuda_runtime.h>
#include <cuda_fp16.h>
#include <math.h>
#include <stdint.h>

// Problem constants
#define BB 4
#define SS 2048
#define DD 512
#define HH 512
#define EE 8
#define TT 8192
#define KSEL 2
#define NPAIR (TT*KSEL)

// GEMM tiling (fp16)
#define BM 128
#define BN 128
#define BKH 64                  // k per tile (halfs) = 128 bytes
#define NKT (512/BKH)           // 8
#define NSTG 3
#define STG_BYTES 16384u        // 128 rows x 128 B
#define SMEM_BYTES (2u*NSTG*STG_BYTES)   // 96 KB

// ---------------- scratch ----------------
__device__ int    g_count[EE];
__device__ int    g_offset[EE+1];
__device__ int    g_cursor[EE];
__device__ int    g_rowtok[NPAIR];
__device__ int    g_pos[NPAIR];
__device__ int    g_topi[NPAIR];
__device__ float  g_gatew[NPAIR];
__device__ __align__(16) __half g_xh[(size_t)TT*DD];       // fp16 x
__device__ __align__(16) __half g_w1t[(size_t)EE*DD*HH];   // fp16 W1^T [e][n][k]
__device__ __align__(16) __half g_w2t[(size_t)EE*HH*DD];   // fp16 W2^T [e][n][k]
__device__ __align__(16) __half g_hh[(size_t)NPAIR*HH];    // fp16 hidden
__device__ __align__(16) float  g_ybuf[(size_t)NPAIR*DD];  // fp32 expert out

// ---------------- helpers ----------------
__device__ __forceinline__ void cp_async16(uint32_t smem_addr, const void* gptr, int src_bytes) {
    asm volatile("cp.async.cg.shared.global [%0], [%1], 16, %2;"
                 :: "r"(smem_addr), "l"(gptr), "r"(src_bytes));
}

// ---------------- conversion kernels ----------------
__global__ void k_cvt_x(const float* __restrict__ src, int n4) {
    int i = blockIdx.x * blockDim.x + threadIdx.x;
    if (i >= n4) return;
    float4 v = ((const float4*)src)[i];
    __half2 h0 = __floats2half2_rn(v.x, v.y);
    __half2 h1 = __floats2half2_rn(v.z, v.w);
    ((__half2*)g_xh)[i*2]   = h0;
    ((__half2*)g_xh)[i*2+1] = h1;
}

// transpose + fp16: dst[e][n][k] = h(src[e][k][n]);  z<8 -> W1, z>=8 -> W2
__global__ void k_transpose(const float* __restrict__ W1, const float* __restrict__ W2) {
    __shared__ float tile[32][33];
    int z = blockIdx.z;
    const float* src = (z < 8) ? W1 + (size_t)z * 262144 : W2 + (size_t)(z - 8) * 262144;
    __half* dst = (z < 8) ? g_w1t + (size_t)z * 262144 : g_w2t + (size_t)(z - 8) * 262144;
    int k0 = blockIdx.x * 32, n0 = blockIdx.y * 32;
    int tx = threadIdx.x, ty = threadIdx.y;   // 32 x 8
#pragma unroll
    for (int i = 0; i < 32; i += 8)
        tile[ty + i][tx] = src[(size_t)(k0 + ty + i) * 512 + n0 + tx];
    __syncthreads();
#pragma unroll
    for (int i = 0; i < 32; i += 8)
        dst[(size_t)(n0 + ty + i) * 512 + k0 + tx] = __float2half_rn(tile[tx][ty + i]);
}

// ---------------- routing kernels ----------------
__global__ void k_zero() {
    int i = threadIdx.x;
    if (i < EE) { g_count[i] = 0; g_cursor[i] = 0; }
}

__global__ void k_gating(const float* __restrict__ x, const float* __restrict__ Wg) {
    int warp = threadIdx.x >> 5, lane = threadIdx.x & 31;
    int t = blockIdx.x * 4 + warp;
    if (t >= TT) return;
    float acc[EE];
#pragma unroll
    for (int e = 0; e < EE; e++) acc[e] = 0.f;
    const float* xr = x + (size_t)t * DD;
    for (int d = lane; d < DD; d += 32) {
        float xv = xr[d];
        float4 w0 = *(const float4*)(Wg + (size_t)d * EE);
        float4 w1 = *(const float4*)(Wg + (size_t)d * EE + 4);
        acc[0] += xv * w0.x; acc[1] += xv * w0.y;
        acc[2] += xv * w0.z; acc[3] += xv * w0.w;
        acc[4] += xv * w1.x; acc[5] += xv * w1.y;
        acc[6] += xv * w1.z; acc[7] += xv * w1.w;
    }
#pragma unroll
    for (int off = 16; off; off >>= 1)
#pragma unroll
        for (int e = 0; e < EE; e++)
            acc[e] += __shfl_down_sync(0xffffffffu, acc[e], off);
    if (lane == 0) {
        int i0 = 0; float v0 = acc[0];
#pragma unroll
        for (int e = 1; e < EE; e++) if (acc[e] > v0) { v0 = acc[e]; i0 = e; }
        int i1 = -1; float v1 = -INFINITY;
#pragma unroll
        for (int e = 0; e < EE; e++) if (e != i0 && acc[e] > v1) { v1 = acc[e]; i1 = e; }
        float e1 = expf(v1 - v0);
        float w0w = 1.f / (1.f + e1);
        float w1w = e1 * w0w;
        g_topi[2*t] = i0; g_topi[2*t+1] = i1;
        g_gatew[2*t] = w0w; g_gatew[2*t+1] = w1w;
        atomicAdd(&g_count[i0], 1);
        atomicAdd(&g_count[i1], 1);
    }
}

__global__ void k_offsets() {
    if (threadIdx.x == 0) {
        int s = 0;
        for (int e = 0; e < EE; e++) { g_offset[e] = s; g_cursor[e] = s; s += g_count[e]; }
        g_offset[EE] = s;
    }
}

__global__ void k_scatter() {
    int p = blockIdx.x * blockDim.x + threadIdx.x;
    if (p >= NPAIR) return;
    int e = g_topi[p];
    int slot = atomicAdd(&g_cursor[e], 1);
    g_rowtok[slot] = p >> 1;
    g_pos[p] = slot;
}

// ---------------- fp16 tensor-core grouped GEMM ----------------
// MODE 0: g_hh[slot]  = h(relu(xh[rowtok] @ W1t[e]^T + b1[e]))
// MODE 1: g_ybuf[slot] =        hh[slot] @ W2t[e]^T + b2[e]
template <int MODE>
__global__ void __launch_bounds__(256, 2)
k_gemm_h(const __half* __restrict__ Wt, const float* __restrict__ Bias) {
    const int e = blockIdx.z;
    const int count = g_count[e];
    const int m0 = blockIdx.y * BM;
    if (m0 >= count) return;
    const int base = g_offset[e];
    const int n0 = blockIdx.x * BN;
    const char* Wp = (const char*)(Wt + (size_t)e * 512 * 512);
    const float* bp = Bias + (size_t)e * 512;

    extern __shared__ char smem[];
    uint32_t sbase = (uint32_t)__cvta_generic_to_shared(smem);
    uint32_t aBase = sbase;
    uint32_t bBase = sbase + NSTG * STG_BYTES;

    const int tid = threadIdx.x;
    const int lane = tid & 31, wid = tid >> 5;
    const int warp_m = wid & 3, warp_n = wid >> 2;
    const int gid = lane >> 2, tk = lane & 3;

    // ---- producer addressing: thread handles 4 (row,chunk) pairs per operand ----
    const int chA = tid & 7;                 // 16B chunk within 128B row
    uint32_t dstOff[4];
    const char* aSrc[4]; int aOk[4];
    const char* bSrc[4];
#pragma unroll
    for (int p = 0; p < 4; p++) {
        int row = (tid >> 3) + 32 * p;       // 0..127
        dstOff[p] = (uint32_t)row * 128u + (uint32_t)((chA ^ (row & 7)) << 4);
        int m = m0 + row;
        if (m < count) {
            if (MODE == 0)
                aSrc[p] = (const char*)(g_xh + (size_t)g_rowtok[base + m] * 512) + chA * 16;
            else
                aSrc[p] = (const char*)(g_hh + (size_t)(base + m) * 512) + chA * 16;
            aOk[p] = 16;
        } else { aSrc[p] = (const char*)g_xh; aOk[p] = 0; }
        bSrc[p] = Wp + (size_t)(n0 + row) * 1024 + chA * 16;
    }

    auto issue = [&](int kt) {
        uint32_t sA = aBase + (uint32_t)(kt % NSTG) * STG_BYTES;
        uint32_t sB = bBase + (uint32_t)(kt % NSTG) * STG_BYTES;
        uint32_t koff = (uint32_t)kt * 128u;
#pragma unroll
        for (int p = 0; p < 4; p++) {
            cp_async16(sA + dstOff[p], aSrc[p] + koff, aOk[p]);
            cp_async16(sB + dstOff[p], bSrc[p] + koff, 16);
        }
        asm volatile("cp.async.commit_group;");
    };

    float acc[2][8][4];
#pragma unroll
    for (int mf = 0; mf < 2; mf++)
#pragma unroll
        for (int nf = 0; nf < 8; nf++)
#pragma unroll
            for (int q = 0; q < 4; q++) acc[mf][nf][q] = 0.f;

    issue(0); issue(1);

    // ldmatrix lane geometry
    const int lg = lane >> 3, lr = lane & 7;

    for (int kt = 0; kt < NKT; kt++) {
        if (kt + 2 < NKT) issue(kt + 2);
        else asm volatile("cp.async.commit_group;");
        asm volatile("cp.async.wait_group 2;");
        __syncthreads();

        uint32_t sA = aBase + (uint32_t)(kt % NSTG) * STG_BYTES;
        uint32_t sB = bBase + (uint32_t)(kt % NSTG) * STG_BYTES;

#pragma unroll
        for (int kf = 0; kf < 4; kf++) {
            // A fragments: mf 0,1 ; matrices: {m0..7,kc0},{m8..15,kc0},{m0..7,kc1},{m8..15,kc1}
            uint32_t a[2][4];
#pragma unroll
            for (int mf = 0; mf < 2; mf++) {
                int mrow = warp_m * 32 + mf * 16 + (lg & 1) * 8 + lr;
                int ch = kf * 2 + (lg >> 1);
                uint32_t addr = sA + (uint32_t)mrow * 128u + (uint32_t)((ch ^ (mrow & 7)) << 4);
                asm volatile("ldmatrix.sync.aligned.m8n8.x4.shared.b16 {%0,%1,%2,%3}, [%4];"
                             : "=r"(a[mf][0]), "=r"(a[mf][1]), "=r"(a[mf][2]), "=r"(a[mf][3])
                             : "r"(addr));
            }
            // B fragments: np covers nf pair (2np, 2np+1)
#pragma unroll
            for (int np = 0; np < 4; np++) {
                int nrow = warp_n * 64 + np * 16 + (lg >> 1) * 8 + lr;
                int ch = kf * 2 + (lg & 1);
                uint32_t addr = sB + (uint32_t)nrow * 128u + (uint32_t)((ch ^ (nrow & 7)) << 4);
                uint32_t b0, b1, b2, b3;
                asm volatile("ldmatrix.sync.aligned.m8n8.x4.shared.b16 {%0,%1,%2,%3}, [%4];"
                             : "=r"(b0), "=r"(b1), "=r"(b2), "=r"(b3)
                             : "r"(addr));
#pragma unroll
                for (int mf = 0; mf < 2; mf++) {
                    asm volatile(
                        "mma.sync.aligned.m16n8k16.row.col.f32.f16.f16.f32 "
                        "{%0,%1,%2,%3}, {%4,%5,%6,%7}, {%8,%9}, {%0,%1,%2,%3};"
                        : "+f"(acc[mf][2*np][0]), "+f"(acc[mf][2*np][1]),
                          "+f"(acc[mf][2*np][2]), "+f"(acc[mf][2*np][3])
                        : "r"(a[mf][0]), "r"(a[mf][1]), "r"(a[mf][2]), "r"(a[mf][3]),
                          "r"(b0), "r"(b1));
                    asm volatile(
                        "mma.sync.aligned.m16n8k16.row.col.f32.f16.f16.f32 "
                        "{%0,%1,%2,%3}, {%4,%5,%6,%7}, {%8,%9}, {%0,%1,%2,%3};"
                        : "+f"(acc[mf][2*np+1][0]), "+f"(acc[mf][2*np+1][1]),
                          "+f"(acc[mf][2*np+1][2]), "+f"(acc[mf][2*np+1][3])
                        : "r"(a[mf][0]), "r"(a[mf][1]), "r"(a[mf][2]), "r"(a[mf][3]),
                          "r"(b2), "r"(b3));
                }
            }
        }
        __syncthreads();
    }

    // ---- epilogue ----
#pragma unroll
    for (int nf = 0; nf < 8; nf++) {
        int c = n0 + warp_n * 64 + nf * 8 + tk * 2;
        float2 bv = *(const float2*)(bp + c);
#pragma unroll
        for (int mf = 0; mf < 2; mf++) {
            int r0 = m0 + warp_m * 32 + mf * 16 + gid;
            int r1 = r0 + 8;
            if (r0 < count) {
                float vx = acc[mf][nf][0] + bv.x;
                float vy = acc[mf][nf][1] + bv.y;
                if (MODE == 0) {
                    __half2 h = __floats2half2_rn(fmaxf(vx, 0.f), fmaxf(vy, 0.f));
                    *(__half2*)(g_hh + (size_t)(base + r0) * 512 + c) = h;
                } else {
                    *(float2*)(g_ybuf + (size_t)(base + r0) * 512 + c) = make_float2(vx, vy);
                }
            }
            if (r1 < count) {
                float vx = acc[mf][nf][2] + bv.x;
                float vy = acc[mf][nf][3] + bv.y;
                if (MODE == 0) {
                    __half2 h = __floats2half2_rn(fmaxf(vx, 0.f), fmaxf(vy, 0.f));
                    *(__half2*)(g_hh + (size_t)(base + r1) * 512 + c) = h;
                } else {
                    *(float2*)(g_ybuf + (size_t)(base + r1) * 512 + c) = make_float2(vx, vy);
                }
            }
        }
    }
}

// ---------------- LayerNorm + combine ----------------
__global__ void k_combine(const float* __restrict__ gamma,
                          const float* __restrict__ beta,
                          float* __restrict__ out) {
    int t = blockIdx.x;
    int tid = threadIdx.x;
    int lane = tid & 31, wid = tid >> 5;
    __shared__ float wred[8][2];
    __shared__ float red[2];
    float o0 = 0.f, o1 = 0.f;
#pragma unroll
    for (int k = 0; k < KSEL; k++) {
        int slot = g_pos[2 * t + k];
        int e = g_topi[2 * t + k];
        float w = g_gatew[2 * t + k];
        const float* yr = g_ybuf + (size_t)slot * 512;
        float y0 = yr[tid], y1 = yr[tid + 256];
        float s = y0 + y1, ss = y0 * y0 + y1 * y1;
#pragma unroll
        for (int off = 16; off; off >>= 1) {
            s  += __shfl_down_sync(0xffffffffu, s, off);
            ss += __shfl_down_sync(0xffffffffu, ss, off);
        }
        if (lane == 0) { wred[wid][0] = s; wred[wid][1] = ss; }
        __syncthreads();
        if (tid == 0) {
            float ts = 0.f, tss = 0.f;
#pragma unroll
            for (int i = 0; i < 8; i++) { ts += wred[i][0]; tss += wred[i][1]; }
            red[0] = ts; red[1] = tss;
        }
        __syncthreads();
        float mu = red[0] * (1.f / 512.f);
        float var = red[1] * (1.f / 512.f) - mu * mu;
        float rstd = rsqrtf(var + 1e-5f);
        const float* gp = gamma + (size_t)e * 512;
        const float* bpp = beta + (size_t)e * 512;
        o0 += w * ((y0 - mu) * rstd * gp[tid] + bpp[tid]);
        o1 += w * ((y1 - mu) * rstd * gp[tid + 256] + bpp[tid + 256]);
        __syncthreads();
    }
    out[(size_t)t * 512 + tid] = o0;
    out[(size_t)t * 512 + tid + 256] = o1;
}

// ---------------- launch ----------------
extern "C" void kernel_launch(void* const* d_in, const int* in_sizes, int n_in,
                              void* d_out, int out_size) {
    const float* x     = (const float*)d_in[0];
    const float* Wg    = (const float*)d_in[1];
    const float* W1    = (const float*)d_in[2];
    const float* b1    = (const float*)d_in[3];
    const float* W2    = (const float*)d_in[4];
    const float* b2    = (const float*)d_in[5];
    const float* gamma = (const float*)d_in[6];
    const float* beta  = (const float*)d_in[7];
    float* out = (float*)d_out;

    static int configured = 0;
    if (!configured) {
        cudaFuncSetAttribute(k_gemm_h<0>, cudaFuncAttributeMaxDynamicSharedMemorySize, SMEM_BYTES);
        cudaFuncSetAttribute(k_gemm_h<1>, cudaFuncAttributeMaxDynamicSharedMemorySize, SMEM_BYTES);
        configured = 1;
    }
    const __half* w1t; cudaGetSymbolAddress((void**)&w1t, g_w1t);
    const __half* w2t; cudaGetSymbolAddress((void**)&w2t, g_w2t);

    k_cvt_x<<<(TT*DD/4 + 255)/256, 256>>>(x, TT*DD/4);
    k_transpose<<<dim3(16, 16, 16), dim3(32, 8)>>>(W1, W2);

    k_zero<<<1, 32>>>();
    k_gating<<<TT / 4, 128>>>(x, Wg);
    k_offsets<<<1, 1>>>();
    k_scatter<<<NPAIR / 256, 256>>>();

    dim3 gg(4, 128, EE);
    k_gemm_h<0><<<gg, 256, SMEM_BYTES>>>(w1t, b1);
    k_gemm_h<1><<<gg, 256, SMEM_BYTES>>>(w2t, b2);
    k_combine<<<TT, 256>>>(gamma, beta, out);
}

// round 5
// speedup vs baseline: 4.3454x; 1.0582x over previous
#include <cuda_runtime.h>
#include <cuda_fp16.h>
#include <math.h>
#include <stdint.h>

// Problem constants
#define BB 4
#define SS 2048
#define DD 512
#define HH 512
#define EE 8
#define TT 8192
#define KSEL 2
#define NPAIR (TT*KSEL)

// GEMM tiling (fp16)
#define BM 128
#define BN 128
#define BKH 64                  // k per tile (halfs) = 128 bytes
#define NKT (512/BKH)           // 8
#define NSTG 3
#define STG_BYTES 16384u        // 128 rows x 128 B
#define SMEM_BYTES (2u*NSTG*STG_BYTES)   // 96 KB

// ---------------- scratch ----------------
__device__ int    g_count[EE];
__device__ int    g_offset[EE+1];
__device__ int    g_cursor[EE];
__device__ int    g_rowtok[NPAIR];
__device__ int    g_pos[NPAIR];
__device__ int    g_topi[NPAIR];
__device__ float  g_gatew[NPAIR];
__device__ __align__(16) __half g_xh[(size_t)TT*DD];       // fp16 x
__device__ __align__(16) __half g_w1t[(size_t)EE*DD*HH];   // fp16 W1^T [e][n][k]
__device__ __align__(16) __half g_w2t[(size_t)EE*HH*DD];   // fp16 W2^T [e][n][k]
__device__ __align__(16) __half g_hh[(size_t)NPAIR*HH];    // fp16 hidden
__device__ __align__(16) __half g_ybh[(size_t)NPAIR*DD];   // fp16 expert out

// ---------------- helpers ----------------
__device__ __forceinline__ void cp_async16(uint32_t smem_addr, const void* gptr, int src_bytes) {
    asm volatile("cp.async.cg.shared.global [%0], [%1], 16, %2;"
                 :: "r"(smem_addr), "l"(gptr), "r"(src_bytes));
}

// ---------------- fused gating + x->half conversion ----------------
// 8 warps/block, 1 token/warp. Wg staged transposed+padded in smem.
__global__ void __launch_bounds__(256)
k_gate(const float* __restrict__ x, const float* __restrict__ Wg) {
    __shared__ float wgs[8 * 516];   // [e][d] padded: bank-conflict-free LDS.128
    int tid = threadIdx.x;
    for (int d = tid; d < 512; d += 256) {
        float4 w0 = *(const float4*)(Wg + d * 8);
        float4 w1 = *(const float4*)(Wg + d * 8 + 4);
        wgs[0*516+d] = w0.x; wgs[1*516+d] = w0.y;
        wgs[2*516+d] = w0.z; wgs[3*516+d] = w0.w;
        wgs[4*516+d] = w1.x; wgs[5*516+d] = w1.y;
        wgs[6*516+d] = w1.z; wgs[7*516+d] = w1.w;
    }
    __syncthreads();

    int warp = tid >> 5, lane = tid & 31;
    int t = blockIdx.x * 8 + warp;
    const float* xr = x + (size_t)t * 512;

    // x -> half, coalesced (also warms L1 for the gating loop)
    {
        const float4* xv4 = (const float4*)xr;
        __half2* xh = (__half2*)(g_xh + (size_t)t * 512);
#pragma unroll
        for (int i = 0; i < 4; i++) {
            float4 v = xv4[lane + 32 * i];
            xh[(lane + 32 * i) * 2]     = __floats2half2_rn(v.x, v.y);
            xh[(lane + 32 * i) * 2 + 1] = __floats2half2_rn(v.z, v.w);
        }
    }

    // lane owns expert e over d-quadrant q
    int e = lane & 7, q = lane >> 3;
    const float* wrow = wgs + e * 516;
    float acc = 0.f;
#pragma unroll
    for (int i = 0; i < 32; i++) {
        int d = (q + 4 * i) * 4;
        float4 v = *(const float4*)(xr + d);
        float4 w = *(const float4*)(wrow + d);
        acc += v.x * w.x + v.y * w.y + v.z * w.z + v.w * w.w;
    }
    acc += __shfl_xor_sync(0xffffffffu, acc, 8);
    acc += __shfl_xor_sync(0xffffffffu, acc, 16);
    // lane l holds logit for e = l&7 (replicated over quads)
    float lg[8];
#pragma unroll
    for (int e2 = 0; e2 < 8; e2++) lg[e2] = __shfl_sync(0xffffffffu, acc, e2);

    if (lane == 0) {
        int i0 = 0; float v0 = lg[0];
#pragma unroll
        for (int e2 = 1; e2 < 8; e2++) if (lg[e2] > v0) { v0 = lg[e2]; i0 = e2; }
        int i1 = -1; float v1 = -INFINITY;
#pragma unroll
        for (int e2 = 0; e2 < 8; e2++) if (e2 != i0 && lg[e2] > v1) { v1 = lg[e2]; i1 = e2; }
        float e1 = expf(v1 - v0);
        float w0w = 1.f / (1.f + e1);
        float w1w = e1 * w0w;
        g_topi[2*t] = i0; g_topi[2*t+1] = i1;
        g_gatew[2*t] = w0w; g_gatew[2*t+1] = w1w;
        atomicAdd(&g_count[i0], 1);
        atomicAdd(&g_count[i1], 1);
    }
}

// ---------------- transpose + fp16 weights (+ counter zeroing) ----------------
__global__ void k_transpose(const float* __restrict__ W1, const float* __restrict__ W2) {
    if (blockIdx.x == 0 && blockIdx.y == 0 && blockIdx.z == 0 &&
        threadIdx.y == 0 && threadIdx.x < EE) {
        g_count[threadIdx.x] = 0; g_cursor[threadIdx.x] = 0;
    }
    __shared__ float tile[32][33];
    int z = blockIdx.z;
    const float* src = (z < 8) ? W1 + (size_t)z * 262144 : W2 + (size_t)(z - 8) * 262144;
    __half* dst = (z < 8) ? g_w1t + (size_t)z * 262144 : g_w2t + (size_t)(z - 8) * 262144;
    int k0 = blockIdx.x * 32, n0 = blockIdx.y * 32;
    int tx = threadIdx.x, ty = threadIdx.y;   // 32 x 8
#pragma unroll
    for (int i = 0; i < 32; i += 8)
        tile[ty + i][tx] = src[(size_t)(k0 + ty + i) * 512 + n0 + tx];
    __syncthreads();
#pragma unroll
    for (int i = 0; i < 32; i += 8)
        dst[(size_t)(n0 + ty + i) * 512 + k0 + tx] = __float2half_rn(tile[tx][ty + i]);
}

__global__ void k_offsets() {
    if (threadIdx.x == 0) {
        int s = 0;
        for (int e = 0; e < EE; e++) { g_offset[e] = s; g_cursor[e] = s; s += g_count[e]; }
        g_offset[EE] = s;
    }
}

__global__ void k_scatter() {
    int p = blockIdx.x * blockDim.x + threadIdx.x;
    if (p >= NPAIR) return;
    int e = g_topi[p];
    int slot = atomicAdd(&g_cursor[e], 1);
    g_rowtok[slot] = p >> 1;
    g_pos[p] = slot;
}

// ---------------- fp16 tensor-core grouped GEMM ----------------
// MODE 0: g_hh[slot]  = h(relu(xh[rowtok] @ W1t[e]^T + b1[e]))
// MODE 1: g_ybh[slot] = h(       hh[slot] @ W2t[e]^T + b2[e])
template <int MODE>
__global__ void __launch_bounds__(256, 2)
k_gemm_h(const __half* __restrict__ Wt, const float* __restrict__ Bias) {
    const int e = blockIdx.z;
    const int count = g_count[e];
    const int m0 = blockIdx.y * BM;
    if (m0 >= count) return;
    const int base = g_offset[e];
    const int n0 = blockIdx.x * BN;
    const char* Wp = (const char*)(Wt + (size_t)e * 512 * 512);
    const float* bp = Bias + (size_t)e * 512;

    extern __shared__ char smem[];
    uint32_t sbase = (uint32_t)__cvta_generic_to_shared(smem);
    uint32_t aBase = sbase;
    uint32_t bBase = sbase + NSTG * STG_BYTES;

    const int tid = threadIdx.x;
    const int lane = tid & 31, wid = tid >> 5;
    const int warp_m = wid & 3, warp_n = wid >> 2;
    const int gid = lane >> 2, tk = lane & 3;

    // producer addressing
    const int chA = tid & 7;
    uint32_t dstOff[4];
    const char* aSrc[4]; int aOk[4];
    const char* bSrc[4];
#pragma unroll
    for (int p = 0; p < 4; p++) {
        int row = (tid >> 3) + 32 * p;
        dstOff[p] = (uint32_t)row * 128u + (uint32_t)((chA ^ (row & 7)) << 4);
        int m = m0 + row;
        if (m < count) {
            if (MODE == 0)
                aSrc[p] = (const char*)(g_xh + (size_t)g_rowtok[base + m] * 512) + chA * 16;
            else
                aSrc[p] = (const char*)(g_hh + (size_t)(base + m) * 512) + chA * 16;
            aOk[p] = 16;
        } else { aSrc[p] = (const char*)g_xh; aOk[p] = 0; }
        bSrc[p] = Wp + (size_t)(n0 + row) * 1024 + chA * 16;
    }

    auto issue = [&](int kt) {
        uint32_t sA = aBase + (uint32_t)(kt % NSTG) * STG_BYTES;
        uint32_t sB = bBase + (uint32_t)(kt % NSTG) * STG_BYTES;
        uint32_t koff = (uint32_t)kt * 128u;
#pragma unroll
        for (int p = 0; p < 4; p++) {
            cp_async16(sA + dstOff[p], aSrc[p] + koff, aOk[p]);
            cp_async16(sB + dstOff[p], bSrc[p] + koff, 16);
        }
        asm volatile("cp.async.commit_group;");
    };

    float acc[2][8][4];
#pragma unroll
    for (int mf = 0; mf < 2; mf++)
#pragma unroll
        for (int nf = 0; nf < 8; nf++)
#pragma unroll
            for (int q = 0; q < 4; q++) acc[mf][nf][q] = 0.f;

    issue(0); issue(1);

    const int lg = lane >> 3, lr = lane & 7;

    for (int kt = 0; kt < NKT; kt++) {
        if (kt == NKT - 1) asm volatile("cp.async.wait_group 0;");
        else               asm volatile("cp.async.wait_group 1;");
        __syncthreads();
        if (kt + 2 < NKT) issue(kt + 2);

        uint32_t sA = aBase + (uint32_t)(kt % NSTG) * STG_BYTES;
        uint32_t sB = bBase + (uint32_t)(kt % NSTG) * STG_BYTES;

#pragma unroll
        for (int kf = 0; kf < 4; kf++) {
            uint32_t a[2][4];
#pragma unroll
            for (int mf = 0; mf < 2; mf++) {
                int mrow = warp_m * 32 + mf * 16 + (lg & 1) * 8 + lr;
                int ch = kf * 2 + (lg >> 1);
                uint32_t addr = sA + (uint32_t)mrow * 128u + (uint32_t)((ch ^ (mrow & 7)) << 4);
                asm volatile("ldmatrix.sync.aligned.m8n8.x4.shared.b16 {%0,%1,%2,%3}, [%4];"
                             : "=r"(a[mf][0]), "=r"(a[mf][1]), "=r"(a[mf][2]), "=r"(a[mf][3])
                             : "r"(addr));
            }
#pragma unroll
            for (int np = 0; np < 4; np++) {
                int nrow = warp_n * 64 + np * 16 + (lg >> 1) * 8 + lr;
                int ch = kf * 2 + (lg & 1);
                uint32_t addr = sB + (uint32_t)nrow * 128u + (uint32_t)((ch ^ (nrow & 7)) << 4);
                uint32_t b0, b1, b2, b3;
                asm volatile("ldmatrix.sync.aligned.m8n8.x4.shared.b16 {%0,%1,%2,%3}, [%4];"
                             : "=r"(b0), "=r"(b1), "=r"(b2), "=r"(b3)
                             : "r"(addr));
#pragma unroll
                for (int mf = 0; mf < 2; mf++) {
                    asm volatile(
                        "mma.sync.aligned.m16n8k16.row.col.f32.f16.f16.f32 "
                        "{%0,%1,%2,%3}, {%4,%5,%6,%7}, {%8,%9}, {%0,%1,%2,%3};"
                        : "+f"(acc[mf][2*np][0]), "+f"(acc[mf][2*np][1]),
                          "+f"(acc[mf][2*np][2]), "+f"(acc[mf][2*np][3])
                        : "r"(a[mf][0]), "r"(a[mf][1]), "r"(a[mf][2]), "r"(a[mf][3]),
                          "r"(b0), "r"(b1));
                    asm volatile(
                        "mma.sync.aligned.m16n8k16.row.col.f32.f16.f16.f32 "
                        "{%0,%1,%2,%3}, {%4,%5,%6,%7}, {%8,%9}, {%0,%1,%2,%3};"
                        : "+f"(acc[mf][2*np+1][0]), "+f"(acc[mf][2*np+1][1]),
                          "+f"(acc[mf][2*np+1][2]), "+f"(acc[mf][2*np+1][3])
                        : "r"(a[mf][0]), "r"(a[mf][1]), "r"(a[mf][2]), "r"(a[mf][3]),
                          "r"(b2), "r"(b3));
                }
            }
        }
    }

    // epilogue (fp16 stores both modes)
    __half* outb = (MODE == 0) ? g_hh : g_ybh;
#pragma unroll
    for (int nf = 0; nf < 8; nf++) {
        int c = n0 + warp_n * 64 + nf * 8 + tk * 2;
        float2 bv = *(const float2*)(bp + c);
#pragma unroll
        for (int mf = 0; mf < 2; mf++) {
            int r0 = m0 + warp_m * 32 + mf * 16 + gid;
            int r1 = r0 + 8;
            if (r0 < count) {
                float vx = acc[mf][nf][0] + bv.x;
                float vy = acc[mf][nf][1] + bv.y;
                if (MODE == 0) { vx = fmaxf(vx, 0.f); vy = fmaxf(vy, 0.f); }
                *(__half2*)(outb + (size_t)(base + r0) * 512 + c) = __floats2half2_rn(vx, vy);
            }
            if (r1 < count) {
                float vx = acc[mf][nf][2] + bv.x;
                float vy = acc[mf][nf][3] + bv.y;
                if (MODE == 0) { vx = fmaxf(vx, 0.f); vy = fmaxf(vy, 0.f); }
                *(__half2*)(outb + (size_t)(base + r1) * 512 + c) = __floats2half2_rn(vx, vy);
            }
        }
    }
}

// ---------------- LayerNorm + combine (half y) ----------------
__global__ void k_combine(const float* __restrict__ gamma,
                          const float* __restrict__ beta,
                          float* __restrict__ out) {
    int t = blockIdx.x;
    int tid = threadIdx.x;
    int lane = tid & 31, wid = tid >> 5;
    __shared__ float wred[8][2];
    __shared__ float red[2];
    float o0 = 0.f, o1 = 0.f;
#pragma unroll
    for (int k = 0; k < KSEL; k++) {
        int slot = g_pos[2 * t + k];
        int e = g_topi[2 * t + k];
        float w = g_gatew[2 * t + k];
        __half2 h = ((const __half2*)(g_ybh + (size_t)slot * 512))[tid];
        float y0 = __low2float(h), y1 = __high2float(h);
        float s = y0 + y1, ss = y0 * y0 + y1 * y1;
#pragma unroll
        for (int off = 16; off; off >>= 1) {
            s  += __shfl_down_sync(0xffffffffu, s, off);
            ss += __shfl_down_sync(0xffffffffu, ss, off);
        }
        if (lane == 0) { wred[wid][0] = s; wred[wid][1] = ss; }
        __syncthreads();
        if (tid == 0) {
            float ts = 0.f, tss = 0.f;
#pragma unroll
            for (int i = 0; i < 8; i++) { ts += wred[i][0]; tss += wred[i][1]; }
            red[0] = ts; red[1] = tss;
        }
        __syncthreads();
        float mu = red[0] * (1.f / 512.f);
        float var = red[1] * (1.f / 512.f) - mu * mu;
        float rstd = rsqrtf(var + 1e-5f);
        float2 g2 = *(const float2*)(gamma + (size_t)e * 512 + 2 * tid);
        float2 b2v = *(const float2*)(beta + (size_t)e * 512 + 2 * tid);
        o0 += w * ((y0 - mu) * rstd * g2.x + b2v.x);
        o1 += w * ((y1 - mu) * rstd * g2.y + b2v.y);
        __syncthreads();
    }
    *(float2*)(out + (size_t)t * 512 + 2 * tid) = make_float2(o0, o1);
}

// ---------------- launch ----------------
extern "C" void kernel_launch(void* const* d_in, const int* in_sizes, int n_in,
                              void* d_out, int out_size) {
    const float* x     = (const float*)d_in[0];
    const float* Wg    = (const float*)d_in[1];
    const float* W1    = (const float*)d_in[2];
    const float* b1    = (const float*)d_in[3];
    const float* W2    = (const float*)d_in[4];
    const float* b2    = (const float*)d_in[5];
    const float* gamma = (const float*)d_in[6];
    const float* beta  = (const float*)d_in[7];
    float* out = (float*)d_out;

    static int configured = 0;
    if (!configured) {
        cudaFuncSetAttribute(k_gemm_h<0>, cudaFuncAttributeMaxDynamicSharedMemorySize, SMEM_BYTES);
        cudaFuncSetAttribute(k_gemm_h<1>, cudaFuncAttributeMaxDynamicSharedMemorySize, SMEM_BYTES);
        configured = 1;
    }
    const __half* w1t; cudaGetSymbolAddress((void**)&w1t, g_w1t);
    const __half* w2t; cudaGetSymbolAddress((void**)&w2t, g_w2t);

    k_transpose<<<dim3(16, 16, 16), dim3(32, 8)>>>(W1, W2);  // also zeroes counters
    k_gate<<<TT / 8, 256>>>(x, Wg);                          // gating + x->half
    k_offsets<<<1, 1>>>();
    k_scatter<<<NPAIR / 256, 256>>>();

    dim3 gg(4, 128, EE);
    k_gemm_h<0><<<gg, 256, SMEM_BYTES>>>(w1t, b1);
    k_gemm_h<1><<<gg, 256, SMEM_BYTES>>>(w2t, b2);
    k_combine<<<TT, 256>>>(gamma, beta, out);
}

// round 6
// speedup vs baseline: 4.4313x; 1.0198x over previous
#include <cuda_runtime.h>
#include <cuda_fp16.h>
#include <math.h>
#include <stdint.h>

// Problem constants
#define BB 4
#define SS 2048
#define DD 512
#define HH 512
#define EE 8
#define TT 8192
#define KSEL 2
#define NPAIR (TT*KSEL)

// GEMM tiling (fp16)
#define BM 128
#define BN 128
#define BKH 64                  // k per tile (halfs) = 128 bytes
#define NKT (512/BKH)           // 8
#define NSTG 3
#define STG_BYTES 16384u        // 128 rows x 128 B
#define SMEM_BYTES (2u*NSTG*STG_BYTES)   // 96 KB

// ---------------- scratch ----------------
__device__ int    g_count[EE];
__device__ int    g_cursor[EE];
__device__ int    g_rowtok[NPAIR];
__device__ int    g_pos[NPAIR];
__device__ int    g_topi[NPAIR];
__device__ float  g_gatew[NPAIR];
__device__ __align__(16) __half g_xh[(size_t)TT*DD];       // fp16 x
__device__ __align__(16) __half g_w1t[(size_t)EE*DD*HH];   // fp16 W1^T [e][n][k]
__device__ __align__(16) __half g_w2t[(size_t)EE*HH*DD];   // fp16 W2^T [e][n][k]
__device__ __align__(16) __half g_hh[(size_t)NPAIR*HH];    // fp16 hidden
__device__ __align__(16) __half g_ybh[(size_t)NPAIR*DD];   // fp16 expert out

// ---------------- helpers ----------------
__device__ __forceinline__ void cp_async16(uint32_t smem_addr, const void* gptr, int src_bytes) {
    asm volatile("cp.async.cg.shared.global [%0], [%1], 16, %2;"
                 :: "r"(smem_addr), "l"(gptr), "r"(src_bytes));
}

// ---------------- fused gating + x->half conversion ----------------
__global__ void __launch_bounds__(256)
k_gate(const float* __restrict__ x, const float* __restrict__ Wg) {
    __shared__ float wgs[8 * 516];
    int tid = threadIdx.x;
    for (int d = tid; d < 512; d += 256) {
        float4 w0 = *(const float4*)(Wg + d * 8);
        float4 w1 = *(const float4*)(Wg + d * 8 + 4);
        wgs[0*516+d] = w0.x; wgs[1*516+d] = w0.y;
        wgs[2*516+d] = w0.z; wgs[3*516+d] = w0.w;
        wgs[4*516+d] = w1.x; wgs[5*516+d] = w1.y;
        wgs[6*516+d] = w1.z; wgs[7*516+d] = w1.w;
    }
    __syncthreads();

    int warp = tid >> 5, lane = tid & 31;
    int t = blockIdx.x * 8 + warp;
    const float* xr = x + (size_t)t * 512;

    // x -> half, coalesced
    {
        const float4* xv4 = (const float4*)xr;
        __half2* xh = (__half2*)(g_xh + (size_t)t * 512);
#pragma unroll
        for (int i = 0; i < 4; i++) {
            float4 v = xv4[lane + 32 * i];
            xh[(lane + 32 * i) * 2]     = __floats2half2_rn(v.x, v.y);
            xh[(lane + 32 * i) * 2 + 1] = __floats2half2_rn(v.z, v.w);
        }
    }

    int e = lane & 7, q = lane >> 3;
    const float* wrow = wgs + e * 516;
    float acc = 0.f;
#pragma unroll
    for (int i = 0; i < 32; i++) {
        int d = (q + 4 * i) * 4;
        float4 v = *(const float4*)(xr + d);
        float4 w = *(const float4*)(wrow + d);
        acc += v.x * w.x + v.y * w.y + v.z * w.z + v.w * w.w;
    }
    acc += __shfl_xor_sync(0xffffffffu, acc, 8);
    acc += __shfl_xor_sync(0xffffffffu, acc, 16);
    float lg[8];
#pragma unroll
    for (int e2 = 0; e2 < 8; e2++) lg[e2] = __shfl_sync(0xffffffffu, acc, e2);

    if (lane == 0) {
        int i0 = 0; float v0 = lg[0];
#pragma unroll
        for (int e2 = 1; e2 < 8; e2++) if (lg[e2] > v0) { v0 = lg[e2]; i0 = e2; }
        int i1 = -1; float v1 = -INFINITY;
#pragma unroll
        for (int e2 = 0; e2 < 8; e2++) if (e2 != i0 && lg[e2] > v1) { v1 = lg[e2]; i1 = e2; }
        float e1 = expf(v1 - v0);
        float w0w = 1.f / (1.f + e1);
        float w1w = e1 * w0w;
        g_topi[2*t] = i0; g_topi[2*t+1] = i1;
        g_gatew[2*t] = w0w; g_gatew[2*t+1] = w1w;
        atomicAdd(&g_count[i0], 1);
        atomicAdd(&g_count[i1], 1);
    }
}

// ---------------- transpose + fp16 weights (+ counter zeroing) ----------------
__global__ void k_transpose(const float* __restrict__ W1, const float* __restrict__ W2) {
    if (blockIdx.x == 0 && blockIdx.y == 0 && blockIdx.z == 0 &&
        threadIdx.y == 0 && threadIdx.x < EE) {
        g_count[threadIdx.x] = 0; g_cursor[threadIdx.x] = 0;
    }
    __shared__ float tile[32][33];
    int z = blockIdx.z;
    const float* src = (z < 8) ? W1 + (size_t)z * 262144 : W2 + (size_t)(z - 8) * 262144;
    __half* dst = (z < 8) ? g_w1t + (size_t)z * 262144 : g_w2t + (size_t)(z - 8) * 262144;
    int k0 = blockIdx.x * 32, n0 = blockIdx.y * 32;
    int tx = threadIdx.x, ty = threadIdx.y;
#pragma unroll
    for (int i = 0; i < 32; i += 8)
        tile[ty + i][tx] = src[(size_t)(k0 + ty + i) * 512 + n0 + tx];
    __syncthreads();
#pragma unroll
    for (int i = 0; i < 32; i += 8)
        dst[(size_t)(n0 + ty + i) * 512 + k0 + tx] = __float2half_rn(tile[tx][ty + i]);
}

// ---------------- scatter (inline prefix over 8 counters) ----------------
__global__ void k_scatter() {
    int p = blockIdx.x * blockDim.x + threadIdx.x;
    if (p >= NPAIR) return;
    int e = g_topi[p];
    int off = 0;
#pragma unroll
    for (int j = 0; j < EE; j++) { int c = g_count[j]; off += (j < e) ? c : 0; }
    int slot = off + atomicAdd(&g_cursor[e], 1);
    g_rowtok[slot] = p >> 1;
    g_pos[p] = slot;
}

// ---------------- fp16 tensor-core grouped GEMM ----------------
// MODE 0: g_hh[slot]  = h(relu(xh[rowtok] @ W1t[e]^T + b1[e]))
// MODE 1: g_ybh[slot] = h(       hh[slot] @ W2t[e]^T + b2[e])
template <int MODE>
__global__ void __launch_bounds__(256, 2)
k_gemm_h(const __half* __restrict__ Wt, const float* __restrict__ Bias) {
    const int e = blockIdx.z;
    const int count = g_count[e];
    const int m0 = blockIdx.y * BM;
    if (m0 >= count) return;
    int base = 0;
#pragma unroll
    for (int j = 0; j < EE; j++) { int c = g_count[j]; base += (j < e) ? c : 0; }
    const int n0 = blockIdx.x * BN;
    const char* Wp = (const char*)(Wt + (size_t)e * 512 * 512);
    const float* bp = Bias + (size_t)e * 512;

    extern __shared__ char smem[];
    uint32_t sbase = (uint32_t)__cvta_generic_to_shared(smem);
    uint32_t aBase = sbase;
    uint32_t bBase = sbase + NSTG * STG_BYTES;

    const int tid = threadIdx.x;
    const int lane = tid & 31, wid = tid >> 5;
    const int warp_m = wid & 3, warp_n = wid >> 2;
    const int gid = lane >> 2, tk = lane & 3;

    const int chA = tid & 7;
    uint32_t dstOff[4];
    const char* aSrc[4]; int aOk[4];
    const char* bSrc[4];
#pragma unroll
    for (int p = 0; p < 4; p++) {
        int row = (tid >> 3) + 32 * p;
        dstOff[p] = (uint32_t)row * 128u + (uint32_t)((chA ^ (row & 7)) << 4);
        int m = m0 + row;
        if (m < count) {
            if (MODE == 0)
                aSrc[p] = (const char*)(g_xh + (size_t)g_rowtok[base + m] * 512) + chA * 16;
            else
                aSrc[p] = (const char*)(g_hh + (size_t)(base + m) * 512) + chA * 16;
            aOk[p] = 16;
        } else { aSrc[p] = (const char*)g_xh; aOk[p] = 0; }
        bSrc[p] = Wp + (size_t)(n0 + row) * 1024 + chA * 16;
    }

    auto issue = [&](int kt) {
        uint32_t sA = aBase + (uint32_t)(kt % NSTG) * STG_BYTES;
        uint32_t sB = bBase + (uint32_t)(kt % NSTG) * STG_BYTES;
        uint32_t koff = (uint32_t)kt * 128u;
#pragma unroll
        for (int p = 0; p < 4; p++) {
            cp_async16(sA + dstOff[p], aSrc[p] + koff, aOk[p]);
            cp_async16(sB + dstOff[p], bSrc[p] + koff, 16);
        }
        asm volatile("cp.async.commit_group;");
    };

    float acc[2][8][4];
#pragma unroll
    for (int mf = 0; mf < 2; mf++)
#pragma unroll
        for (int nf = 0; nf < 8; nf++)
#pragma unroll
            for (int q = 0; q < 4; q++) acc[mf][nf][q] = 0.f;

    issue(0); issue(1);

    const int lg = lane >> 3, lr = lane & 7;

    for (int kt = 0; kt < NKT; kt++) {
        if (kt == NKT - 1) asm volatile("cp.async.wait_group 0;");
        else               asm volatile("cp.async.wait_group 1;");
        __syncthreads();
        if (kt + 2 < NKT) issue(kt + 2);

        uint32_t sA = aBase + (uint32_t)(kt % NSTG) * STG_BYTES;
        uint32_t sB = bBase + (uint32_t)(kt % NSTG) * STG_BYTES;

#pragma unroll
        for (int kf = 0; kf < 4; kf++) {
            uint32_t a[2][4];
#pragma unroll
            for (int mf = 0; mf < 2; mf++) {
                int mrow = warp_m * 32 + mf * 16 + (lg & 1) * 8 + lr;
                int ch = kf * 2 + (lg >> 1);
                uint32_t addr = sA + (uint32_t)mrow * 128u + (uint32_t)((ch ^ (mrow & 7)) << 4);
                asm volatile("ldmatrix.sync.aligned.m8n8.x4.shared.b16 {%0,%1,%2,%3}, [%4];"
                             : "=r"(a[mf][0]), "=r"(a[mf][1]), "=r"(a[mf][2]), "=r"(a[mf][3])
                             : "r"(addr));
            }
#pragma unroll
            for (int np = 0; np < 4; np++) {
                int nrow = warp_n * 64 + np * 16 + (lg >> 1) * 8 + lr;
                int ch = kf * 2 + (lg & 1);
                uint32_t addr = sB + (uint32_t)nrow * 128u + (uint32_t)((ch ^ (nrow & 7)) << 4);
                uint32_t b0, b1, b2, b3;
                asm volatile("ldmatrix.sync.aligned.m8n8.x4.shared.b16 {%0,%1,%2,%3}, [%4];"
                             : "=r"(b0), "=r"(b1), "=r"(b2), "=r"(b3)
                             : "r"(addr));
#pragma unroll
                for (int mf = 0; mf < 2; mf++) {
                    asm volatile(
                        "mma.sync.aligned.m16n8k16.row.col.f32.f16.f16.f32 "
                        "{%0,%1,%2,%3}, {%4,%5,%6,%7}, {%8,%9}, {%0,%1,%2,%3};"
                        : "+f"(acc[mf][2*np][0]), "+f"(acc[mf][2*np][1]),
                          "+f"(acc[mf][2*np][2]), "+f"(acc[mf][2*np][3])
                        : "r"(a[mf][0]), "r"(a[mf][1]), "r"(a[mf][2]), "r"(a[mf][3]),
                          "r"(b0), "r"(b1));
                    asm volatile(
                        "mma.sync.aligned.m16n8k16.row.col.f32.f16.f16.f32 "
                        "{%0,%1,%2,%3}, {%4,%5,%6,%7}, {%8,%9}, {%0,%1,%2,%3};"
                        : "+f"(acc[mf][2*np+1][0]), "+f"(acc[mf][2*np+1][1]),
                          "+f"(acc[mf][2*np+1][2]), "+f"(acc[mf][2*np+1][3])
                        : "r"(a[mf][0]), "r"(a[mf][1]), "r"(a[mf][2]), "r"(a[mf][3]),
                          "r"(b2), "r"(b3));
                }
            }
        }
    }

    __half* outb = (MODE == 0) ? g_hh : g_ybh;
#pragma unroll
    for (int nf = 0; nf < 8; nf++) {
        int c = n0 + warp_n * 64 + nf * 8 + tk * 2;
        float2 bv = *(const float2*)(bp + c);
#pragma unroll
        for (int mf = 0; mf < 2; mf++) {
            int r0 = m0 + warp_m * 32 + mf * 16 + gid;
            int r1 = r0 + 8;
            if (r0 < count) {
                float vx = acc[mf][nf][0] + bv.x;
                float vy = acc[mf][nf][1] + bv.y;
                if (MODE == 0) { vx = fmaxf(vx, 0.f); vy = fmaxf(vy, 0.f); }
                *(__half2*)(outb + (size_t)(base + r0) * 512 + c) = __floats2half2_rn(vx, vy);
            }
            if (r1 < count) {
                float vx = acc[mf][nf][2] + bv.x;
                float vy = acc[mf][nf][3] + bv.y;
                if (MODE == 0) { vx = fmaxf(vx, 0.f); vy = fmaxf(vy, 0.f); }
                *(__half2*)(outb + (size_t)(base + r1) * 512 + c) = __floats2half2_rn(vx, vy);
            }
        }
    }
}

// ---------------- LayerNorm + combine: warp per token ----------------
__global__ void __launch_bounds__(256)
k_combine(const float* __restrict__ gamma,
          const float* __restrict__ beta,
          float* __restrict__ out) {
    int warp = threadIdx.x >> 5, lane = threadIdx.x & 31;
    int t = blockIdx.x * 8 + warp;

    float o[16];
#pragma unroll
    for (int i = 0; i < 16; i++) o[i] = 0.f;

#pragma unroll
    for (int k = 0; k < KSEL; k++) {
        int slot = g_pos[2 * t + k];
        int e = g_topi[2 * t + k];
        float w = g_gatew[2 * t + k];

        const uint4* yr = (const uint4*)(g_ybh + (size_t)slot * 512);
        uint4 u0 = yr[lane * 2], u1 = yr[lane * 2 + 1];
        float y[16];
        {
            const uint32_t uw[8] = {u0.x, u0.y, u0.z, u0.w, u1.x, u1.y, u1.z, u1.w};
#pragma unroll
            for (int i = 0; i < 8; i++) {
                __half2 h = *(const __half2*)&uw[i];
                y[2*i]   = __low2float(h);
                y[2*i+1] = __high2float(h);
            }
        }
        float s = 0.f, ss = 0.f;
#pragma unroll
        for (int i = 0; i < 16; i++) { s += y[i]; ss += y[i] * y[i]; }
#pragma unroll
        for (int off = 16; off; off >>= 1) {
            s  += __shfl_xor_sync(0xffffffffu, s, off);
            ss += __shfl_xor_sync(0xffffffffu, ss, off);
        }
        float mu = s * (1.f / 512.f);
        float var = ss * (1.f / 512.f) - mu * mu;
        float rstd = rsqrtf(var + 1e-5f);
        float wr = w * rstd;

        const float4* gp = (const float4*)(gamma + (size_t)e * 512) + lane * 4;
        const float4* bpp = (const float4*)(beta + (size_t)e * 512) + lane * 4;
#pragma unroll
        for (int q = 0; q < 4; q++) {
            float4 g4 = gp[q], b4 = bpp[q];
            o[4*q+0] += wr * (y[4*q+0] - mu) * g4.x + w * b4.x;
            o[4*q+1] += wr * (y[4*q+1] - mu) * g4.y + w * b4.y;
            o[4*q+2] += wr * (y[4*q+2] - mu) * g4.z + w * b4.z;
            o[4*q+3] += wr * (y[4*q+3] - mu) * g4.w + w * b4.w;
        }
    }

    float4* op = (float4*)(out + (size_t)t * 512) + lane * 4;
#pragma unroll
    for (int q = 0; q < 4; q++)
        op[q] = make_float4(o[4*q], o[4*q+1], o[4*q+2], o[4*q+3]);
}

// ---------------- launch ----------------
extern "C" void kernel_launch(void* const* d_in, const int* in_sizes, int n_in,
                              void* d_out, int out_size) {
    const float* x     = (const float*)d_in[0];
    const float* Wg    = (const float*)d_in[1];
    const float* W1    = (const float*)d_in[2];
    const float* b1    = (const float*)d_in[3];
    const float* W2    = (const float*)d_in[4];
    const float* b2    = (const float*)d_in[5];
    const float* gamma = (const float*)d_in[6];
    const float* beta  = (const float*)d_in[7];
    float* out = (float*)d_out;

    static int configured = 0;
    if (!configured) {
        cudaFuncSetAttribute(k_gemm_h<0>, cudaFuncAttributeMaxDynamicSharedMemorySize, SMEM_BYTES);
        cudaFuncSetAttribute(k_gemm_h<1>, cudaFuncAttributeMaxDynamicSharedMemorySize, SMEM_BYTES);
        configured = 1;
    }
    const __half* w1t; cudaGetSymbolAddress((void**)&w1t, g_w1t);
    const __half* w2t; cudaGetSymbolAddress((void**)&w2t, g_w2t);

    k_transpose<<<dim3(16, 16, 16), dim3(32, 8)>>>(W1, W2);  // also zeroes counters
    k_gate<<<TT / 8, 256>>>(x, Wg);                          // gating + x->half
    k_scatter<<<NPAIR / 256, 256>>>();                       // inline prefix sums

    dim3 gg(4, 128, EE);
    k_gemm_h<0><<<gg, 256, SMEM_BYTES>>>(w1t, b1);
    k_gemm_h<1><<<gg, 256, SMEM_BYTES>>>(w2t, b2);
    k_combine<<<TT / 8, 256>>>(gamma, beta, out);
}

// round 7
// speedup vs baseline: 4.7651x; 1.0753x over previous
#include <cuda_runtime.h>
#include <cuda_fp16.h>
#include <math.h>
#include <stdint.h>

// Problem constants
#define BB 4
#define SS 2048
#define DD 512
#define HH 512
#define EE 8
#define TT 8192
#define KSEL 2
#define NPAIR (TT*KSEL)
#define ECAP 8192            // per-expert bucket capacity (max possible count)

// GEMM tiling (fp16)
#define BM 128
#define BN 128
#define BKH 64               // k per tile (halfs) = 128 bytes
#define NKT (512/BKH)        // 8
#define NSTG 3
#define STG_BYTES 16384u     // 128 rows x 128 B
#define SMEM_BYTES (2u*NSTG*STG_BYTES)   // 96 KB
#define NPGRID 304           // persistent grid (2 per SM x 152)

// ---------------- scratch ----------------
__device__ int    g_cursor[EE];
__device__ int    g_rowtok[EE*ECAP];
__device__ int    g_pos[NPAIR];
__device__ int    g_topi[NPAIR];
__device__ float  g_gatew[NPAIR];
__device__ __align__(16) __half g_xh[(size_t)TT*DD];         // fp16 x
__device__ __align__(16) __half g_w1t[(size_t)EE*DD*HH];     // fp16 W1^T [e][n][k]
__device__ __align__(16) __half g_w2t[(size_t)EE*HH*DD];     // fp16 W2^T [e][n][k]
__device__ __align__(16) __half g_hh[(size_t)EE*ECAP*HH];    // fp16 hidden (bucketed)
__device__ __align__(16) __half g_ybh[(size_t)EE*ECAP*DD];   // fp16 expert out (bucketed)

// ---------------- helpers ----------------
__device__ __forceinline__ void cp_async16(uint32_t smem_addr, const void* gptr, int src_bytes) {
    asm volatile("cp.async.cg.shared.global [%0], [%1], 16, %2;"
                 :: "r"(smem_addr), "l"(gptr), "r"(src_bytes));
}

// ---------------- fused gating + x->half + slot assignment ----------------
__global__ void __launch_bounds__(256)
k_gate(const float* __restrict__ x, const float* __restrict__ Wg) {
    __shared__ float wgs[8 * 516];
    int tid = threadIdx.x;
    for (int d = tid; d < 512; d += 256) {
        float4 w0 = *(const float4*)(Wg + d * 8);
        float4 w1 = *(const float4*)(Wg + d * 8 + 4);
        wgs[0*516+d] = w0.x; wgs[1*516+d] = w0.y;
        wgs[2*516+d] = w0.z; wgs[3*516+d] = w0.w;
        wgs[4*516+d] = w1.x; wgs[5*516+d] = w1.y;
        wgs[6*516+d] = w1.z; wgs[7*516+d] = w1.w;
    }
    __syncthreads();

    int warp = tid >> 5, lane = tid & 31;
    int t = blockIdx.x * 8 + warp;
    const float* xr = x + (size_t)t * 512;

    // x -> half, coalesced
    {
        const float4* xv4 = (const float4*)xr;
        __half2* xh = (__half2*)(g_xh + (size_t)t * 512);
#pragma unroll
        for (int i = 0; i < 4; i++) {
            float4 v = xv4[lane + 32 * i];
            xh[(lane + 32 * i) * 2]     = __floats2half2_rn(v.x, v.y);
            xh[(lane + 32 * i) * 2 + 1] = __floats2half2_rn(v.z, v.w);
        }
    }

    int e = lane & 7, q = lane >> 3;
    const float* wrow = wgs + e * 516;
    float acc = 0.f;
#pragma unroll
    for (int i = 0; i < 32; i++) {
        int d = (q + 4 * i) * 4;
        float4 v = *(const float4*)(xr + d);
        float4 w = *(const float4*)(wrow + d);
        acc += v.x * w.x + v.y * w.y + v.z * w.z + v.w * w.w;
    }
    acc += __shfl_xor_sync(0xffffffffu, acc, 8);
    acc += __shfl_xor_sync(0xffffffffu, acc, 16);
    float lg[8];
#pragma unroll
    for (int e2 = 0; e2 < 8; e2++) lg[e2] = __shfl_sync(0xffffffffu, acc, e2);

    if (lane == 0) {
        int i0 = 0; float v0 = lg[0];
#pragma unroll
        for (int e2 = 1; e2 < 8; e2++) if (lg[e2] > v0) { v0 = lg[e2]; i0 = e2; }
        int i1 = -1; float v1 = -INFINITY;
#pragma unroll
        for (int e2 = 0; e2 < 8; e2++) if (e2 != i0 && lg[e2] > v1) { v1 = lg[e2]; i1 = e2; }
        float e1 = expf(v1 - v0);
        float w0w = 1.f / (1.f + e1);
        float w1w = e1 * w0w;
        g_topi[2*t] = i0; g_topi[2*t+1] = i1;
        g_gatew[2*t] = w0w; g_gatew[2*t+1] = w1w;
        int s0 = atomicAdd(&g_cursor[i0], 1);
        int s1 = atomicAdd(&g_cursor[i1], 1);
        g_rowtok[i0 * ECAP + s0] = t;
        g_rowtok[i1 * ECAP + s1] = t;
        g_pos[2*t]   = i0 * ECAP + s0;
        g_pos[2*t+1] = i1 * ECAP + s1;
    }
}

// ---------------- transpose + fp16 weights (+ cursor zeroing) ----------------
__global__ void k_transpose(const float* __restrict__ W1, const float* __restrict__ W2) {
    if (blockIdx.x == 0 && blockIdx.y == 0 && blockIdx.z == 0 &&
        threadIdx.y == 0 && threadIdx.x < EE) {
        g_cursor[threadIdx.x] = 0;
    }
    __shared__ float tile[32][33];
    int z = blockIdx.z;
    const float* src = (z < 8) ? W1 + (size_t)z * 262144 : W2 + (size_t)(z - 8) * 262144;
    __half* dst = (z < 8) ? g_w1t + (size_t)z * 262144 : g_w2t + (size_t)(z - 8) * 262144;
    int k0 = blockIdx.x * 32, n0 = blockIdx.y * 32;
    int tx = threadIdx.x, ty = threadIdx.y;
#pragma unroll
    for (int i = 0; i < 32; i += 8)
        tile[ty + i][tx] = src[(size_t)(k0 + ty + i) * 512 + n0 + tx];
    __syncthreads();
#pragma unroll
    for (int i = 0; i < 32; i += 8)
        dst[(size_t)(n0 + ty + i) * 512 + k0 + tx] = __float2half_rn(tile[tx][ty + i]);
}

// ---------------- persistent fp16 tensor-core grouped GEMM ----------------
// MODE 0: g_hh[e*ECAP+slot]  = h(relu(xh[rowtok] @ W1t[e]^T + b1[e]))
// MODE 1: g_ybh[e*ECAP+slot] = h(        hh[...] @ W2t[e]^T + b2[e])
template <int MODE>
__global__ void __launch_bounds__(256, 2)
k_gemm_h(const __half* __restrict__ Wt, const float* __restrict__ Bias) {
    extern __shared__ char smem[];
    uint32_t sbase = (uint32_t)__cvta_generic_to_shared(smem);
    uint32_t aBase = sbase;
    uint32_t bBase = sbase + NSTG * STG_BYTES;

    const int tid = threadIdx.x;
    const int lane = tid & 31, wid = tid >> 5;
    const int warp_m = wid & 3, warp_n = wid >> 2;
    const int gid = lane >> 2, tk = lane & 3;
    const int lg = lane >> 3, lr = lane & 7;
    const int chA = tid & 7;

    // total items
    int total = 0;
#pragma unroll
    for (int j = 0; j < EE; j++) total += ((g_cursor[j] + 127) >> 7) * 4;

    for (int item = blockIdx.x; item < total; item += NPGRID) {
        // decode (e, mtile, ntile); n fastest for A reuse in L2
        int rem = item, e = 0, count = 0;
#pragma unroll
        for (int j = 0; j < EE; j++) {
            int c = g_cursor[j];
            int tiles = ((c + 127) >> 7) * 4;
            if (rem >= 0) { e = j; count = c; if (rem < tiles) { /* found */ } }
            if (rem >= tiles) rem -= tiles; else if (j < EE) { if (e == j) break; }
        }
        // simpler scan (the above unrolls poorly): redo linearly
        rem = item; e = 0;
        while (e < EE) {
            count = g_cursor[e];
            int tiles = ((count + 127) >> 7) * 4;
            if (rem < tiles) break;
            rem -= tiles; e++;
        }
        const int m0 = (rem >> 2) * BM;
        const int n0 = (rem & 3) * BN;
        const int base = e * ECAP;
        const char* Wp = (const char*)(Wt + (size_t)e * 512 * 512);
        const float* bp = Bias + (size_t)e * 512;

        // producer addressing
        uint32_t dstOff[4];
        const char* aSrc[4]; int aOk[4];
        const char* bSrc[4];
#pragma unroll
        for (int p = 0; p < 4; p++) {
            int row = (tid >> 3) + 32 * p;
            dstOff[p] = (uint32_t)row * 128u + (uint32_t)((chA ^ (row & 7)) << 4);
            int m = m0 + row;
            if (m < count) {
                if (MODE == 0)
                    aSrc[p] = (const char*)(g_xh + (size_t)g_rowtok[base + m] * 512) + chA * 16;
                else
                    aSrc[p] = (const char*)(g_hh + (size_t)(base + m) * 512) + chA * 16;
                aOk[p] = 16;
            } else { aSrc[p] = (const char*)g_xh; aOk[p] = 0; }
            bSrc[p] = Wp + (size_t)(n0 + row) * 1024 + chA * 16;
        }

        auto issue = [&](int kt) {
            uint32_t sA = aBase + (uint32_t)(kt % NSTG) * STG_BYTES;
            uint32_t sB = bBase + (uint32_t)(kt % NSTG) * STG_BYTES;
            uint32_t koff = (uint32_t)kt * 128u;
#pragma unroll
            for (int p = 0; p < 4; p++) {
                cp_async16(sA + dstOff[p], aSrc[p] + koff, aOk[p]);
                cp_async16(sB + dstOff[p], bSrc[p] + koff, 16);
            }
            asm volatile("cp.async.commit_group;");
        };

        float acc[2][8][4];
#pragma unroll
        for (int mf = 0; mf < 2; mf++)
#pragma unroll
            for (int nf = 0; nf < 8; nf++)
#pragma unroll
                for (int q = 0; q < 4; q++) acc[mf][nf][q] = 0.f;

        issue(0); issue(1);

        for (int kt = 0; kt < NKT; kt++) {
            if (kt == NKT - 1) asm volatile("cp.async.wait_group 0;");
            else               asm volatile("cp.async.wait_group 1;");
            __syncthreads();
            if (kt + 2 < NKT) issue(kt + 2);

            uint32_t sA = aBase + (uint32_t)(kt % NSTG) * STG_BYTES;
            uint32_t sB = bBase + (uint32_t)(kt % NSTG) * STG_BYTES;

#pragma unroll
            for (int kf = 0; kf < 4; kf++) {
                uint32_t a[2][4];
#pragma unroll
                for (int mf = 0; mf < 2; mf++) {
                    int mrow = warp_m * 32 + mf * 16 + (lg & 1) * 8 + lr;
                    int ch = kf * 2 + (lg >> 1);
                    uint32_t addr = sA + (uint32_t)mrow * 128u + (uint32_t)((ch ^ (mrow & 7)) << 4);
                    asm volatile("ldmatrix.sync.aligned.m8n8.x4.shared.b16 {%0,%1,%2,%3}, [%4];"
                                 : "=r"(a[mf][0]), "=r"(a[mf][1]), "=r"(a[mf][2]), "=r"(a[mf][3])
                                 : "r"(addr));
                }
#pragma unroll
                for (int np = 0; np < 4; np++) {
                    int nrow = warp_n * 64 + np * 16 + (lg >> 1) * 8 + lr;
                    int ch = kf * 2 + (lg & 1);
                    uint32_t addr = sB + (uint32_t)nrow * 128u + (uint32_t)((ch ^ (nrow & 7)) << 4);
                    uint32_t b0, b1, b2, b3;
                    asm volatile("ldmatrix.sync.aligned.m8n8.x4.shared.b16 {%0,%1,%2,%3}, [%4];"
                                 : "=r"(b0), "=r"(b1), "=r"(b2), "=r"(b3)
                                 : "r"(addr));
#pragma unroll
                    for (int mf = 0; mf < 2; mf++) {
                        asm volatile(
                            "mma.sync.aligned.m16n8k16.row.col.f32.f16.f16.f32 "
                            "{%0,%1,%2,%3}, {%4,%5,%6,%7}, {%8,%9}, {%0,%1,%2,%3};"
                            : "+f"(acc[mf][2*np][0]), "+f"(acc[mf][2*np][1]),
                              "+f"(acc[mf][2*np][2]), "+f"(acc[mf][2*np][3])
                            : "r"(a[mf][0]), "r"(a[mf][1]), "r"(a[mf][2]), "r"(a[mf][3]),
                              "r"(b0), "r"(b1));
                        asm volatile(
                            "mma.sync.aligned.m16n8k16.row.col.f32.f16.f16.f32 "
                            "{%0,%1,%2,%3}, {%4,%5,%6,%7}, {%8,%9}, {%0,%1,%2,%3};"
                            : "+f"(acc[mf][2*np+1][0]), "+f"(acc[mf][2*np+1][1]),
                              "+f"(acc[mf][2*np+1][2]), "+f"(acc[mf][2*np+1][3])
                            : "r"(a[mf][0]), "r"(a[mf][1]), "r"(a[mf][2]), "r"(a[mf][3]),
                              "r"(b2), "r"(b3));
                    }
                }
            }
        }

        // item barrier: all warps done reading stages before next item's issues
        __syncthreads();

        __half* outb = (MODE == 0) ? g_hh : g_ybh;
#pragma unroll
        for (int nf = 0; nf < 8; nf++) {
            int c = n0 + warp_n * 64 + nf * 8 + tk * 2;
            float2 bv = *(const float2*)(bp + c);
#pragma unroll
            for (int mf = 0; mf < 2; mf++) {
                int r0 = m0 + warp_m * 32 + mf * 16 + gid;
                int r1 = r0 + 8;
                if (r0 < count) {
                    float vx = acc[mf][nf][0] + bv.x;
                    float vy = acc[mf][nf][1] + bv.y;
                    if (MODE == 0) { vx = fmaxf(vx, 0.f); vy = fmaxf(vy, 0.f); }
                    *(__half2*)(outb + (size_t)(base + r0) * 512 + c) = __floats2half2_rn(vx, vy);
                }
                if (r1 < count) {
                    float vx = acc[mf][nf][2] + bv.x;
                    float vy = acc[mf][nf][3] + bv.y;
                    if (MODE == 0) { vx = fmaxf(vx, 0.f); vy = fmaxf(vy, 0.f); }
                    *(__half2*)(outb + (size_t)(base + r1) * 512 + c) = __floats2half2_rn(vx, vy);
                }
            }
        }
    }
}

// ---------------- LayerNorm + combine: warp per token ----------------
__global__ void __launch_bounds__(256)
k_combine(const float* __restrict__ gamma,
          const float* __restrict__ beta,
          float* __restrict__ out) {
    int warp = threadIdx.x >> 5, lane = threadIdx.x & 31;
    int t = blockIdx.x * 8 + warp;

    float o[16];
#pragma unroll
    for (int i = 0; i < 16; i++) o[i] = 0.f;

#pragma unroll
    for (int k = 0; k < KSEL; k++) {
        int slot = g_pos[2 * t + k];
        int e = g_topi[2 * t + k];
        float w = g_gatew[2 * t + k];

        const uint4* yr = (const uint4*)(g_ybh + (size_t)slot * 512);
        uint4 u0 = yr[lane * 2], u1 = yr[lane * 2 + 1];
        float y[16];
        {
            const uint32_t uw[8] = {u0.x, u0.y, u0.z, u0.w, u1.x, u1.y, u1.z, u1.w};
#pragma unroll
            for (int i = 0; i < 8; i++) {
                __half2 h = *(const __half2*)&uw[i];
                y[2*i]   = __low2float(h);
                y[2*i+1] = __high2float(h);
            }
        }
        float s = 0.f, ss = 0.f;
#pragma unroll
        for (int i = 0; i < 16; i++) { s += y[i]; ss += y[i] * y[i]; }
#pragma unroll
        for (int off = 16; off; off >>= 1) {
            s  += __shfl_xor_sync(0xffffffffu, s, off);
            ss += __shfl_xor_sync(0xffffffffu, ss, off);
        }
        float mu = s * (1.f / 512.f);
        float var = ss * (1.f / 512.f) - mu * mu;
        float rstd = rsqrtf(var + 1e-5f);
        float wr = w * rstd;

        const float4* gp = (const float4*)(gamma + (size_t)e * 512) + lane * 4;
        const float4* bpp = (const float4*)(beta + (size_t)e * 512) + lane * 4;
#pragma unroll
        for (int q = 0; q < 4; q++) {
            float4 g4 = gp[q], b4 = bpp[q];
            o[4*q+0] += wr * (y[4*q+0] - mu) * g4.x + w * b4.x;
            o[4*q+1] += wr * (y[4*q+1] - mu) * g4.y + w * b4.y;
            o[4*q+2] += wr * (y[4*q+2] - mu) * g4.z + w * b4.z;
            o[4*q+3] += wr * (y[4*q+3] - mu) * g4.w + w * b4.w;
        }
    }

    float4* op = (float4*)(out + (size_t)t * 512) + lane * 4;
#pragma unroll
    for (int q = 0; q < 4; q++)
        op[q] = make_float4(o[4*q], o[4*q+1], o[4*q+2], o[4*q+3]);
}

// ---------------- launch ----------------
extern "C" void kernel_launch(void* const* d_in, const int* in_sizes, int n_in,
                              void* d_out, int out_size) {
    const float* x     = (const float*)d_in[0];
    const float* Wg    = (const float*)d_in[1];
    const float* W1    = (const float*)d_in[2];
    const float* b1    = (const float*)d_in[3];
    const float* W2    = (const float*)d_in[4];
    const float* b2    = (const float*)d_in[5];
    const float* gamma = (const float*)d_in[6];
    const float* beta  = (const float*)d_in[7];
    float* out = (float*)d_out;

    static int configured = 0;
    if (!configured) {
        cudaFuncSetAttribute(k_gemm_h<0>, cudaFuncAttributeMaxDynamicSharedMemorySize, SMEM_BYTES);
        cudaFuncSetAttribute(k_gemm_h<1>, cudaFuncAttributeMaxDynamicSharedMemorySize, SMEM_BYTES);
        configured = 1;
    }
    const __half* w1t; cudaGetSymbolAddress((void**)&w1t, g_w1t);
    const __half* w2t; cudaGetSymbolAddress((void**)&w2t, g_w2t);

    k_transpose<<<dim3(16, 16, 16), dim3(32, 8)>>>(W1, W2);  // also zeroes cursors
    k_gate<<<TT / 8, 256>>>(x, Wg);                          // gating + cvt + slots

    k_gemm_h<0><<<NPGRID, 256, SMEM_BYTES>>>(w1t, b1);
    k_gemm_h<1><<<NPGRID, 256, SMEM_BYTES>>>(w2t, b2);
    k_combine<<<TT / 8, 256>>>(gamma, beta, out);
}